// round 2
// baseline (speedup 1.0000x reference)
#include <cuda_runtime.h>
#include <cstdint>
#include <math.h>

// ---------------------------------------------------------------------------
// Problem dims (fixed by the dataset)
// ---------------------------------------------------------------------------
#define BB 64
#define TT 512
#define DD 1024
#define HH 1024
#define SIXH (6 * HH)
#define FIVEH (5 * HH)
#define BTH (BB * TT * HH)      // 33,554,432
#define BH (BB * HH)            // 65,536

// Recurrent kernel config
#define NBLK 128                // persistent blocks (<=148 SMs -> co-resident)
#define JCH 8                   // hidden columns per block (NBLK*JCH = HH)
#define KC 64                   // k-chunk staged in smem

// ---------------------------------------------------------------------------
// Device scratch (static allocations only — no cudaMalloc allowed)
// ---------------------------------------------------------------------------
__device__ __align__(16) float g_pi[201326592];   // (B*T, 6H) = 805 MB, reused per layer
__device__ __align__(16) float g_y0[BTH];         // layer-0 output (B,T,H)
__device__ __align__(16) float g_Wpk[NBLK * HH * (5 * JCH)]; // packed recurrent weights
__device__ __align__(16) float g_hT[2][HH * BB];  // ping-pong h, transposed: [k][b]

__device__ unsigned g_barc = 0;
__device__ unsigned g_barf = 0;

__device__ __forceinline__ float sigf(float x) { return 1.f / (1.f + expf(-x)); }

// Epoch-based grid barrier (all NBLK blocks co-resident; 1 per time step)
__device__ __forceinline__ void grid_barrier(unsigned ep) {
    __syncthreads();
    if (threadIdx.x == 0) {
        __threadfence();
        unsigned old = atomicAdd(&g_barc, 1u);
        if (old == gridDim.x - 1) {
            g_barc = 0;
            __threadfence();
            atomicExch(&g_barf, ep);
        } else {
            while ((int)(*(volatile unsigned*)&g_barf - ep) < 0) {
                __nanosleep(32);
            }
        }
    }
    __syncthreads();
}

// ---------------------------------------------------------------------------
// Pack Ws (H x 5H row-major) -> g_Wpk[jb][k][w*5+g] = Ws[k][g*H + jb*8 + w]
// ---------------------------------------------------------------------------
__global__ void pack_kernel(const float* __restrict__ Ws) {
    int idx = blockIdx.x * blockDim.x + threadIdx.x;
    const int total = NBLK * HH * (5 * JCH);
    if (idx >= total) return;
    int jb = idx / (HH * 40);
    int rem = idx - jb * (HH * 40);
    int k = rem / 40;
    int c = rem - k * 40;
    int w = c / 5;
    int g = c - w * 5;
    g_Wpk[idx] = Ws[(size_t)k * FIVEH + g * HH + jb * JCH + w];
}

// ---------------------------------------------------------------------------
// fp32 SIMT GEMM: C(MxN) = A(MxK) * W(KxN), all row-major.
// 128x128 tile, bk=8, 256 threads, 8x8 micro-tile. Writes into g_pi.
// ---------------------------------------------------------------------------
__global__ __launch_bounds__(256, 2) void gemm_kernel(
    const float* __restrict__ A, const float* __restrict__ W,
    int M, int N, int K)
{
    __shared__ __align__(16) float As[8][128];
    __shared__ __align__(16) float Bs[8][128];

    const int tid = threadIdx.x;
    const int m0 = blockIdx.y * 128;
    const int n0 = blockIdx.x * 128;
    const int arow = tid >> 1;
    const int acol = (tid & 1) * 4;
    const int brow = tid >> 5;
    const int bcol = (tid & 31) * 4;
    const int ty = tid >> 4;
    const int tx = tid & 15;

    float acc[8][8];
    #pragma unroll
    for (int i = 0; i < 8; i++)
        #pragma unroll
        for (int j = 0; j < 8; j++) acc[i][j] = 0.f;

    const float* Ap = A + (size_t)(m0 + arow) * K + acol;
    const float* Wp = W + (size_t)brow * N + n0 + bcol;

    for (int k0 = 0; k0 < K; k0 += 8) {
        float4 av = *(const float4*)(Ap + k0);
        As[acol + 0][arow] = av.x;
        As[acol + 1][arow] = av.y;
        As[acol + 2][arow] = av.z;
        As[acol + 3][arow] = av.w;
        *(float4*)&Bs[brow][bcol] = *(const float4*)(Wp + (size_t)k0 * N);
        __syncthreads();
        #pragma unroll
        for (int kk = 0; kk < 8; kk++) {
            float a[8], b[8];
            *(float4*)&a[0] = *(const float4*)&As[kk][ty * 8];
            *(float4*)&a[4] = *(const float4*)&As[kk][ty * 8 + 4];
            *(float4*)&b[0] = *(const float4*)&Bs[kk][tx * 8];
            *(float4*)&b[4] = *(const float4*)&Bs[kk][tx * 8 + 4];
            #pragma unroll
            for (int i = 0; i < 8; i++)
                #pragma unroll
                for (int j = 0; j < 8; j++)
                    acc[i][j] = fmaf(a[i], b[j], acc[i][j]);
        }
        __syncthreads();
    }

    #pragma unroll
    for (int i = 0; i < 8; i++) {
        float* cp = g_pi + (size_t)(m0 + ty * 8 + i) * N + n0 + tx * 8;
        *(float4*)cp = make_float4(acc[i][0], acc[i][1], acc[i][2], acc[i][3]);
        *(float4*)(cp + 4) = make_float4(acc[i][4], acc[i][5], acc[i][6], acc[i][7]);
    }
}

// ---------------------------------------------------------------------------
// Persistent recurrent kernel: one launch covers all T time steps of a layer.
// Block jb owns hidden columns j = jb*8 .. jb*8+7 (one column per warp).
// Each lane owns batch rows (lane, lane+32) -> c,h kept in registers.
// h published transposed in global ping-pong buffers g_hT[.][k][b].
// ---------------------------------------------------------------------------
__global__ __launch_bounds__(256, 1) void rec_kernel(
    const float* __restrict__ bs, const int* __restrict__ lengths,
    float* __restrict__ y, float* __restrict__ outh, float* __restrict__ outc)
{
    __shared__ __align__(16) float hs[KC][BB];
    __shared__ __align__(16) float ws[KC][40];
    __shared__ unsigned s_base;

    const int tid = threadIdx.x;
    const int w = tid >> 5;
    const int lane = tid & 31;
    const int jb = blockIdx.x;
    const int j = jb * JCH + w;
    const int r0 = lane;
    const int r1 = lane + 32;

    if (tid == 0) s_base = *(volatile unsigned*)&g_barf;

    const int len0 = lengths[r0];
    const int len1 = lengths[r1];

    float bias[5];
    #pragma unroll
    for (int g = 0; g < 5; g++) bias[g] = bs[g * HH + j];

    // zero this block's columns of h buffer 0 (initial hidden state)
    g_hT[0][jb * (JCH * BB) + tid] = 0.f;
    g_hT[0][jb * (JCH * BB) + 256 + tid] = 0.f;

    __syncthreads();
    unsigned ep = s_base;
    grid_barrier(++ep);

    const float* Wb = g_Wpk + (size_t)jb * (HH * 40);

    float h0 = 0.f, h1 = 0.f, c0 = 0.f, c1 = 0.f;

    for (int t = 0; t < TT; t++) {
        const float* hTr = g_hT[t & 1];
        float* hTw = g_hT[(t + 1) & 1];

        // Prefetch input projections for this step (hidden under GEMM latency)
        float p0[6], p1[6];
        {
            const float* pr0 = g_pi + ((size_t)r0 * TT + t) * SIXH + j;
            const float* pr1 = g_pi + ((size_t)r1 * TT + t) * SIXH + j;
            #pragma unroll
            for (int g = 0; g < 6; g++) {
                p0[g] = pr0[g * HH];
                p1[g] = pr1[g * HH];
            }
        }

        float a0[5], a1[5];
        #pragma unroll
        for (int g = 0; g < 5; g++) { a0[g] = bias[g]; a1[g] = bias[g]; }

        for (int k0 = 0; k0 < HH; k0 += KC) {
            // stage h chunk (contiguous in transposed layout; bypass L1 w/ ldcg)
            const float4* hsrc = (const float4*)(hTr + k0 * BB);
            float4* hdst = (float4*)&hs[0][0];
            #pragma unroll
            for (int i = 0; i < 4; i++)
                hdst[tid + i * 256] = __ldcg(hsrc + tid + i * 256);
            // stage packed weight chunk (contiguous)
            const float4* wsrc = (const float4*)(Wb + (size_t)k0 * 40);
            float4* wdst = (float4*)&ws[0][0];
            #pragma unroll
            for (int i = 0; i < 3; i++) {
                int idx = tid + i * 256;
                if (idx < 640) wdst[idx] = wsrc[idx];
            }
            __syncthreads();
            #pragma unroll 4
            for (int kk = 0; kk < KC; kk++) {
                float hv0 = hs[kk][r0];
                float hv1 = hs[kk][r1];
                #pragma unroll
                for (int g = 0; g < 5; g++) {
                    float wv = ws[kk][w * 5 + g];
                    a0[g] = fmaf(wv, hv0, a0[g]);
                    a1[g] = fmaf(wv, hv1, a1[g]);
                }
            }
            __syncthreads();
        }

        // gate math, row r0
        {
            float ig = sigf(p0[0] + a0[0]);
            float fg = sigf(p0[1] + a0[1]);
            float mi = tanhf(p0[2] + a0[2]);
            float og = sigf(p0[3] + a0[3]);
            float cn = ig * mi + fg * c0;
            float o = og * tanhf(cn);
            float hg = sigf(p0[4] + a0[4]);
            o = hg * o + (1.f - hg) * p0[5];
            bool v = (t < len0);
            if (v) { c0 = cn; h0 = o; }
            y[((size_t)r0 * TT + t) * HH + j] = v ? o : 0.f;
        }
        // gate math, row r1
        {
            float ig = sigf(p1[0] + a1[0]);
            float fg = sigf(p1[1] + a1[1]);
            float mi = tanhf(p1[2] + a1[2]);
            float og = sigf(p1[3] + a1[3]);
            float cn = ig * mi + fg * c1;
            float o = og * tanhf(cn);
            float hg = sigf(p1[4] + a1[4]);
            o = hg * o + (1.f - hg) * p1[5];
            bool v = (t < len1);
            if (v) { c1 = cn; h1 = o; }
            y[((size_t)r1 * TT + t) * HH + j] = v ? o : 0.f;
        }

        // publish h for next step (other buffer -> single barrier per step)
        __stcg(&hTw[j * BB + r0], h0);
        __stcg(&hTw[j * BB + r1], h1);

        grid_barrier(++ep);
    }

    // final states
    outh[(size_t)r0 * HH + j] = h0;
    outh[(size_t)r1 * HH + j] = h1;
    outc[(size_t)r0 * HH + j] = c0;
    outc[(size_t)r1 * HH + j] = c1;
}

// ---------------------------------------------------------------------------
// Launcher
// ---------------------------------------------------------------------------
extern "C" void kernel_launch(void* const* d_in, const int* in_sizes, int n_in,
                              void* d_out, int out_size)
{
    (void)in_sizes; (void)n_in; (void)out_size;
    const float* x   = (const float*)d_in[0];
    const int*   len = (const int*)d_in[1];
    const float* Wi0 = (const float*)d_in[2];
    const float* Ws0 = (const float*)d_in[3];
    const float* bs0 = (const float*)d_in[4];
    const float* Wi1 = (const float*)d_in[5];
    const float* Ws1 = (const float*)d_in[6];
    const float* bs1 = (const float*)d_in[7];
    float* out = (float*)d_out;

    float* y0_ptr = nullptr;
    cudaGetSymbolAddress((void**)&y0_ptr, g_y0);

    float* outh = out + BTH;            // (2,B,H)
    float* outc = out + BTH + 2 * BH;   // (2,B,H)

    const int pack_total = NBLK * HH * (5 * JCH);
    dim3 ggrid(SIXH / 128, (BB * TT) / 128);

    // ---- layer 0 ----
    pack_kernel<<<(pack_total + 255) / 256, 256>>>(Ws0);
    gemm_kernel<<<ggrid, 256>>>(x, Wi0, BB * TT, SIXH, DD);
    rec_kernel<<<NBLK, 256>>>(bs0, len, y0_ptr, outh, outc);

    // ---- layer 1 ----
    pack_kernel<<<(pack_total + 255) / 256, 256>>>(Ws1);
    gemm_kernel<<<ggrid, 256>>>(y0_ptr, Wi1, BB * TT, SIXH, HH);
    rec_kernel<<<NBLK, 256>>>(bs1, len, out, outh + BH, outc + BH);
}

// round 5
// speedup vs baseline: 1.2261x; 1.2261x over previous
#include <cuda_runtime.h>
#include <cuda_bf16.h>
#include <cstdint>
#include <math.h>

#define BB 64
#define TT 512
#define DD 1024
#define HH 1024
#define SIXH (6 * HH)
#define FIVEH (5 * HH)
#define BTH (BB * TT * HH)
#define BH (BB * HH)

#define NBLK 128
#define JCH 8
#define KC 64

// mma.sync GEMM: C[32768,6144] = A'[32768,3072]_bf16 x B'[6144,3072]^T, fp32 acc
#define GK 3072
#define GKC 64                 // bf16 per K-chunk = 128B row (SW128 atom)
#define GNCHUNK (GK / GKC)     // 48
#define GMT 128
#define GNT 256
#define GSTAGE 49152           // 16KB A + 32KB B per stage
#define SMEM_GEMM (2 * GSTAGE) // 96KB
#define SWZ(x) ((x) ^ (((x) >> 3) & 0x70))

__device__ __align__(16) float g_pi[201326592];
__device__ __align__(16) float g_y0[BTH];
__device__ __align__(16) float g_Wpk[NBLK * HH * (5 * JCH)];
__device__ __align__(16) float g_hT[2][HH * BB];
__device__ __align__(16) __nv_bfloat16 g_Abf[98304ull * 1024ull];  // 32768 x 3072
__device__ __align__(16) __nv_bfloat16 g_Bbf[6144ull * 3072ull];

__device__ unsigned g_barc = 0;
__device__ unsigned g_barf = 0;

__device__ __forceinline__ float sigf(float x) { return 1.f / (1.f + expf(-x)); }

__device__ __forceinline__ uint32_t smem_u32(const void* p) {
    uint32_t a;
    asm("{ .reg .u64 t; cvta.to.shared.u64 t, %1; cvt.u32.u64 %0, t; }" : "=r"(a) : "l"(p));
    return a;
}
__device__ __forceinline__ void cp_async16(uint32_t d, const void* g) {
    asm volatile("cp.async.cg.shared.global [%0], [%1], 16;" :: "r"(d), "l"(g));
}
__device__ __forceinline__ void ldsm_x4(uint32_t addr, uint32_t& r0, uint32_t& r1,
                                        uint32_t& r2, uint32_t& r3) {
    asm volatile("ldmatrix.sync.aligned.m8n8.x4.shared.b16 {%0,%1,%2,%3}, [%4];"
                 : "=r"(r0), "=r"(r1), "=r"(r2), "=r"(r3) : "r"(addr));
}
__device__ __forceinline__ void mma16816(float* c, const uint32_t* a, const uint32_t* b) {
    asm volatile("mma.sync.aligned.m16n8k16.row.col.f32.bf16.bf16.f32 "
                 "{%0,%1,%2,%3}, {%4,%5,%6,%7}, {%8,%9}, {%0,%1,%2,%3};"
                 : "+f"(c[0]), "+f"(c[1]), "+f"(c[2]), "+f"(c[3])
                 : "r"(a[0]), "r"(a[1]), "r"(a[2]), "r"(a[3]), "r"(b[0]), "r"(b[1]));
}

__device__ __forceinline__ void grid_barrier(unsigned ep) {
    __syncthreads();
    if (threadIdx.x == 0) {
        __threadfence();
        unsigned old = atomicAdd(&g_barc, 1u);
        if (old == gridDim.x - 1) {
            g_barc = 0;
            __threadfence();
            atomicExch(&g_barf, ep);
        } else {
            while ((int)(*(volatile unsigned*)&g_barf - ep) < 0) __nanosleep(32);
        }
    }
    __syncthreads();
}

// A' = [hi | lo | hi] along K (row-major)
__global__ void convA_kernel(const float* __restrict__ src, __nv_bfloat16* __restrict__ dst) {
    size_t i = (size_t)blockIdx.x * blockDim.x + threadIdx.x;
    int m = (int)(i >> 9), r = (int)(i & 511);
    float2 a = ((const float2*)src)[i];
    __nv_bfloat162 hi, lo;
    hi.x = __float2bfloat16(a.x); hi.y = __float2bfloat16(a.y);
    lo.x = __float2bfloat16(a.x - __bfloat162float(hi.x));
    lo.y = __float2bfloat16(a.y - __bfloat162float(hi.y));
    __nv_bfloat162* d = (__nv_bfloat162*)dst + (size_t)m * 1536;
    d[r] = hi; d[512 + r] = lo; d[1024 + r] = hi;
}

// B'[n] = [hi | hi | lo] of W[:,n] (transpose via smem)
__global__ void convB_kernel(const float* __restrict__ W, __nv_bfloat16* __restrict__ dst) {
    __shared__ float t[32][33];
    int nb = blockIdx.x * 32, kb = blockIdx.y * 32;
    int tx = threadIdx.x & 31, ty = threadIdx.x >> 5;
    #pragma unroll
    for (int i = 0; i < 4; i++)
        t[ty + i * 8][tx] = W[(size_t)(kb + ty + i * 8) * SIXH + nb + tx];
    __syncthreads();
    #pragma unroll
    for (int i = 0; i < 4; i++) {
        int ny = ty + i * 8;
        float a = t[tx][ny];
        __nv_bfloat16 hi = __float2bfloat16(a);
        __nv_bfloat16 lo = __float2bfloat16(a - __bfloat162float(hi));
        __nv_bfloat16* dr = dst + (size_t)(nb + ny) * GK;
        dr[kb + tx] = hi; dr[1024 + kb + tx] = hi; dr[2048 + kb + tx] = lo;
    }
}

// ---------------------------------------------------------------------------
// bf16 mma.sync GEMM, tile 128x256x64, 16 warps (2m x 8n), warp tile 64x32.
// ---------------------------------------------------------------------------
__global__ void __launch_bounds__(512, 1) gemm_mma(const __nv_bfloat16* __restrict__ A,
                                                   const __nv_bfloat16* __restrict__ B) {
    extern __shared__ __align__(1024) char sm[];
    const uint32_t sbase = smem_u32(sm);
    const int tid = threadIdx.x, wid = tid >> 5, lane = tid & 31;
    const int n0 = blockIdx.x * GNT, m0 = blockIdx.y * GMT;
    const int m_warp = (wid & 1) * 64;      // 2 warps in m
    const int n_warp = (wid >> 1) * 32;     // 8 warps in n

    // per-lane ldmatrix address precompute
    const int ahalf = lane >> 4;            // 16B column half for A
    const int bhalf = (lane >> 3) & 1;      // 16B column half for B
    int aoff[4], a7[4], boff[2], b7[2];
    #pragma unroll
    for (int mt = 0; mt < 4; mt++) {
        int r = m_warp + mt * 16 + (lane & 15);
        aoff[mt] = r * 128; a7[mt] = r & 7;
    }
    #pragma unroll
    for (int bt = 0; bt < 2; bt++) {
        int r = n_warp + bt * 16 + (lane & 7) + ((lane >> 4) << 3);
        boff[bt] = r * 128; b7[bt] = r & 7;
    }

    float acc[4][4][4];
    #pragma unroll
    for (int i = 0; i < 4; i++)
        #pragma unroll
        for (int j = 0; j < 4; j++)
            #pragma unroll
            for (int k = 0; k < 4; k++) acc[i][j][k] = 0.f;

    auto load_chunk = [&](int kc, int buf) {
        uint32_t sa = sbase + buf * GSTAGE;
        uint32_t sb = sa + 16384;
        const char* ga = (const char*)(A + (size_t)m0 * GK + kc * GKC);
        const char* gb = (const char*)(B + (size_t)n0 * GK + kc * GKC);
        #pragma unroll
        for (int i = 0; i < 2; i++) {       // A: 128 rows x 8 x 16B = 1024
            int idx = tid + i * 512, r = idx >> 3, c = idx & 7;
            cp_async16(sa + r * 128 + (((c ^ (r & 7)) << 4)), ga + (size_t)r * (GK * 2) + c * 16);
        }
        #pragma unroll
        for (int i = 0; i < 4; i++) {       // B: 256 rows x 8 x 16B = 2048
            int idx = tid + i * 512, r = idx >> 3, c = idx & 7;
            cp_async16(sb + r * 128 + (((c ^ (r & 7)) << 4)), gb + (size_t)r * (GK * 2) + c * 16);
        }
        asm volatile("cp.async.commit_group;" ::: "memory");
    };

    load_chunk(0, 0);
    for (int kc = 0; kc < GNCHUNK; kc++) {
        int buf = kc & 1;
        if (kc + 1 < GNCHUNK) {
            load_chunk(kc + 1, buf ^ 1);
            asm volatile("cp.async.wait_group 1;" ::: "memory");
        } else {
            asm volatile("cp.async.wait_group 0;" ::: "memory");
        }
        __syncthreads();

        uint32_t saA = sbase + buf * GSTAGE;
        uint32_t saB = saA + 16384;
        #pragma unroll
        for (int ks = 0; ks < 4; ks++) {
            uint32_t a[4][4], b[4][2];
            #pragma unroll
            for (int mt = 0; mt < 4; mt++) {
                uint32_t addr = saA + aoff[mt] + ((((ks << 1) + ahalf) ^ a7[mt]) << 4);
                ldsm_x4(addr, a[mt][0], a[mt][1], a[mt][2], a[mt][3]);
            }
            #pragma unroll
            for (int bt = 0; bt < 2; bt++) {
                uint32_t addr = saB + boff[bt] + ((((ks << 1) + bhalf) ^ b7[bt]) << 4);
                ldsm_x4(addr, b[2 * bt][0], b[2 * bt][1], b[2 * bt + 1][0], b[2 * bt + 1][1]);
            }
            #pragma unroll
            for (int mt = 0; mt < 4; mt++)
                #pragma unroll
                for (int nt = 0; nt < 4; nt++)
                    mma16816(acc[mt][nt], a[mt], b[nt]);
        }
        __syncthreads();
    }

    // Epilogue: direct float2 stores (32B sectors fully covered)
    #pragma unroll
    for (int mt = 0; mt < 4; mt++) {
        int m = m0 + m_warp + mt * 16 + (lane >> 2);
        #pragma unroll
        for (int nt = 0; nt < 4; nt++) {
            int n = n0 + n_warp + nt * 8 + (lane & 3) * 2;
            float2 v0 = make_float2(acc[mt][nt][0], acc[mt][nt][1]);
            float2 v1 = make_float2(acc[mt][nt][2], acc[mt][nt][3]);
            *(float2*)(g_pi + (size_t)m * SIXH + n) = v0;
            *(float2*)(g_pi + (size_t)(m + 8) * SIXH + n) = v1;
        }
    }
}

__global__ void pack_kernel(const float* __restrict__ Ws) {
    int idx = blockIdx.x * blockDim.x + threadIdx.x;
    if (idx >= NBLK * HH * 40) return;
    int jb = idx / (HH * 40);
    int rem = idx - jb * (HH * 40);
    int k = rem / 40, c = rem - (rem / 40) * 40;
    int w = c / 5, g = c - w * 5;
    g_Wpk[idx] = Ws[(size_t)k * FIVEH + g * HH + jb * JCH + w];
}

__global__ void __launch_bounds__(256, 1) rec_kernel(
    const float* __restrict__ bs, const int* __restrict__ lengths,
    float* __restrict__ y, float* __restrict__ outh, float* __restrict__ outc)
{
    __shared__ __align__(16) float hs[KC][BB];
    __shared__ __align__(16) float ws[KC][40];
    __shared__ unsigned s_base;

    const int tid = threadIdx.x, w = tid >> 5, lane = tid & 31;
    const int jb = blockIdx.x, j = jb * JCH + w;
    const int r0 = lane, r1 = lane + 32;

    if (tid == 0) s_base = *(volatile unsigned*)&g_barf;
    const int len0 = lengths[r0], len1 = lengths[r1];

    float bias[5];
    #pragma unroll
    for (int g = 0; g < 5; g++) bias[g] = bs[g * HH + j];

    g_hT[0][jb * (JCH * BB) + tid] = 0.f;
    g_hT[0][jb * (JCH * BB) + 256 + tid] = 0.f;

    __syncthreads();
    unsigned ep = s_base;
    grid_barrier(++ep);

    const float* Wb = g_Wpk + (size_t)jb * (HH * 40);
    float h0 = 0.f, h1 = 0.f, c0 = 0.f, c1 = 0.f;

    for (int t = 0; t < TT; t++) {
        const float* hTr = g_hT[t & 1];
        float* hTw = g_hT[(t + 1) & 1];

        float p0[6], p1[6];
        {
            const float* pr0 = g_pi + ((size_t)r0 * TT + t) * SIXH + j;
            const float* pr1 = g_pi + ((size_t)r1 * TT + t) * SIXH + j;
            #pragma unroll
            for (int g = 0; g < 6; g++) { p0[g] = pr0[g * HH]; p1[g] = pr1[g * HH]; }
        }

        float a0[5], a1[5];
        #pragma unroll
        for (int g = 0; g < 5; g++) { a0[g] = bias[g]; a1[g] = bias[g]; }

        for (int k0 = 0; k0 < HH; k0 += KC) {
            const float4* hsrc = (const float4*)(hTr + k0 * BB);
            float4* hdst = (float4*)&hs[0][0];
            #pragma unroll
            for (int i = 0; i < 4; i++) hdst[tid + i * 256] = __ldcg(hsrc + tid + i * 256);
            const float4* wsrc = (const float4*)(Wb + (size_t)k0 * 40);
            float4* wdst = (float4*)&ws[0][0];
            #pragma unroll
            for (int i = 0; i < 3; i++) {
                int idx = tid + i * 256;
                if (idx < 640) wdst[idx] = wsrc[idx];
            }
            __syncthreads();
            #pragma unroll 4
            for (int kk = 0; kk < KC; kk++) {
                float hv0 = hs[kk][r0], hv1 = hs[kk][r1];
                #pragma unroll
                for (int g = 0; g < 5; g++) {
                    float wv = ws[kk][w * 5 + g];
                    a0[g] = fmaf(wv, hv0, a0[g]);
                    a1[g] = fmaf(wv, hv1, a1[g]);
                }
            }
            __syncthreads();
        }

        {
            float ig = sigf(p0[0] + a0[0]), fg = sigf(p0[1] + a0[1]);
            float mi = tanhf(p0[2] + a0[2]), og = sigf(p0[3] + a0[3]);
            float cn = ig * mi + fg * c0;
            float o = og * tanhf(cn);
            float hg = sigf(p0[4] + a0[4]);
            o = hg * o + (1.f - hg) * p0[5];
            bool v = (t < len0);
            if (v) { c0 = cn; h0 = o; }
            y[((size_t)r0 * TT + t) * HH + j] = v ? o : 0.f;
        }
        {
            float ig = sigf(p1[0] + a1[0]), fg = sigf(p1[1] + a1[1]);
            float mi = tanhf(p1[2] + a1[2]), og = sigf(p1[3] + a1[3]);
            float cn = ig * mi + fg * c1;
            float o = og * tanhf(cn);
            float hg = sigf(p1[4] + a1[4]);
            o = hg * o + (1.f - hg) * p1[5];
            bool v = (t < len1);
            if (v) { c1 = cn; h1 = o; }
            y[((size_t)r1 * TT + t) * HH + j] = v ? o : 0.f;
        }

        __stcg(&hTw[j * BB + r0], h0);
        __stcg(&hTw[j * BB + r1], h1);
        grid_barrier(++ep);
    }

    outh[(size_t)r0 * HH + j] = h0;
    outh[(size_t)r1 * HH + j] = h1;
    outc[(size_t)r0 * HH + j] = c0;
    outc[(size_t)r1 * HH + j] = c1;
}

extern "C" void kernel_launch(void* const* d_in, const int* in_sizes, int n_in,
                              void* d_out, int out_size)
{
    (void)in_sizes; (void)n_in; (void)out_size;
    const float* x   = (const float*)d_in[0];
    const int*   len = (const int*)d_in[1];
    const float* Wi0 = (const float*)d_in[2];
    const float* Ws0 = (const float*)d_in[3];
    const float* bs0 = (const float*)d_in[4];
    const float* Wi1 = (const float*)d_in[5];
    const float* Ws1 = (const float*)d_in[6];
    const float* bs1 = (const float*)d_in[7];
    float* out = (float*)d_out;

    float* y0_ptr = nullptr;
    cudaGetSymbolAddress((void**)&y0_ptr, g_y0);
    __nv_bfloat16* abf = nullptr; cudaGetSymbolAddress((void**)&abf, g_Abf);
    __nv_bfloat16* bbf = nullptr; cudaGetSymbolAddress((void**)&bbf, g_Bbf);

    cudaFuncSetAttribute(gemm_mma, cudaFuncAttributeMaxDynamicSharedMemorySize, SMEM_GEMM);

    float* outh = out + BTH;
    float* outc = out + BTH + 2 * BH;

    const int pack_total = NBLK * HH * 40;
    dim3 ggrid(SIXH / GNT, (BB * TT) / GMT);
    dim3 cbgrid(SIXH / 32, 1024 / 32);
    const int convA_blocks = (int)(((size_t)32768 * 512) / 256);

    // ---- layer 0 ----
    pack_kernel<<<(pack_total + 255) / 256, 256>>>(Ws0);
    convA_kernel<<<convA_blocks, 256>>>(x, abf);
    convB_kernel<<<cbgrid, 256>>>(Wi0, bbf);
    gemm_mma<<<ggrid, 512, SMEM_GEMM>>>(abf, bbf);
    rec_kernel<<<NBLK, 256>>>(bs0, len, y0_ptr, outh, outc);

    // ---- layer 1 ----
    pack_kernel<<<(pack_total + 255) / 256, 256>>>(Ws1);
    convA_kernel<<<convA_blocks, 256>>>(y0_ptr, abf);
    convB_kernel<<<cbgrid, 256>>>(Wi1, bbf);
    gemm_mma<<<ggrid, 512, SMEM_GEMM>>>(abf, bbf);
    rec_kernel<<<NBLK, 256>>>(bs1, len, out, outh + BH, outc + BH);
}

// round 7
// speedup vs baseline: 2.6623x; 2.1713x over previous
#include <cuda_runtime.h>
#include <cuda_bf16.h>
#include <cstdint>
#include <math.h>

#define BB 64
#define TT 512
#define DD 1024
#define HH 1024
#define SIXH (6 * HH)
#define FIVEH (5 * HH)
#define BTH (BB * TT * HH)
#define BH (BB * HH)

#define NBLK 128

// input-projection GEMM (unchanged from R5)
#define GK 3072
#define GKC 64
#define GNCHUNK (GK / GKC)
#define GMT 128
#define GNT 256
#define GSTAGE 49152
#define SMEM_GEMM (2 * GSTAGE)

// recurrent mma kernel
#define NSTG 4
#define STGB 18432                  // A 8192 + W1 5120 + W2 5120
#define PS_OFF (NSTG * STGB)        // 73728
#define PS_PAD 42
#define SMEM_REC (PS_OFF + 2 * 64 * PS_PAD * 4)   // 95232

__device__ __align__(16) float g_pi[201326592];
__device__ __align__(16) float g_y0[BTH];
__device__ __align__(16) __nv_bfloat16 g_Abf[98304ull * 1024ull];
__device__ __align__(16) __nv_bfloat16 g_Bbf[6144ull * 3072ull];
__device__ __align__(128) __nv_bfloat16 g_Wr[128ull * 32ull * 2560ull];  // packed rec weights
__device__ __align__(128) __nv_bfloat16 g_Ah[2][131072];                 // h split [hi|lo], swizzled chunks

__device__ unsigned g_barc = 0;
__device__ unsigned g_barf = 0;

__device__ __forceinline__ float sigf(float x) { return 1.f / (1.f + expf(-x)); }

__device__ __forceinline__ uint32_t smem_u32(const void* p) {
    uint32_t a;
    asm("{ .reg .u64 t; cvta.to.shared.u64 t, %1; cvt.u32.u64 %0, t; }" : "=r"(a) : "l"(p));
    return a;
}
__device__ __forceinline__ void cp_async16(uint32_t d, const void* g) {
    asm volatile("cp.async.cg.shared.global [%0], [%1], 16;" :: "r"(d), "l"(g));
}
__device__ __forceinline__ void ldsm_x4(uint32_t addr, uint32_t& r0, uint32_t& r1,
                                        uint32_t& r2, uint32_t& r3) {
    asm volatile("ldmatrix.sync.aligned.m8n8.x4.shared.b16 {%0,%1,%2,%3}, [%4];"
                 : "=r"(r0), "=r"(r1), "=r"(r2), "=r"(r3) : "r"(addr));
}
__device__ __forceinline__ void ldsm_x2(uint32_t addr, uint32_t& r0, uint32_t& r1) {
    asm volatile("ldmatrix.sync.aligned.m8n8.x2.shared.b16 {%0,%1}, [%2];"
                 : "=r"(r0), "=r"(r1) : "r"(addr));
}
__device__ __forceinline__ void mma16816(float* c, const uint32_t* a, const uint32_t* b) {
    asm volatile("mma.sync.aligned.m16n8k16.row.col.f32.bf16.bf16.f32 "
                 "{%0,%1,%2,%3}, {%4,%5,%6,%7}, {%8,%9}, {%0,%1,%2,%3};"
                 : "+f"(c[0]), "+f"(c[1]), "+f"(c[2]), "+f"(c[3])
                 : "r"(a[0]), "r"(a[1]), "r"(a[2]), "r"(a[3]), "r"(b[0]), "r"(b[1]));
}
__device__ __forceinline__ void mbar_init(uint32_t a, uint32_t c) {
    asm volatile("mbarrier.init.shared.b64 [%0], %1;" :: "r"(a), "r"(c) : "memory");
}
__device__ __forceinline__ void mbar_expect(uint32_t a, uint32_t bytes) {
    asm volatile("mbarrier.arrive.expect_tx.shared.b64 _, [%0], %1;" :: "r"(a), "r"(bytes) : "memory");
}
__device__ __forceinline__ void mbar_wait(uint32_t a, uint32_t par) {
    uint32_t done;
    asm volatile("{\n\t.reg .pred p;\n\t"
                 "mbarrier.try_wait.parity.acquire.cta.shared::cta.b64 p, [%1], %2;\n\t"
                 "selp.b32 %0,1,0,p;\n\t}" : "=r"(done) : "r"(a), "r"(par) : "memory");
    while (!done) {
        asm volatile("{\n\t.reg .pred p;\n\t"
                     "mbarrier.try_wait.parity.acquire.cta.shared::cta.b64 p, [%1], %2, 0x989680;\n\t"
                     "selp.b32 %0,1,0,p;\n\t}" : "=r"(done) : "r"(a), "r"(par) : "memory");
    }
}
__device__ __forceinline__ void bulk_g2s(uint32_t dst, const void* src, uint32_t bytes, uint32_t mbar) {
    asm volatile("cp.async.bulk.shared::cluster.global.mbarrier::complete_tx::bytes [%0], [%1], %2, [%3];"
                 :: "r"(dst), "l"(src), "r"(bytes), "r"(mbar) : "memory");
}

__device__ __forceinline__ void grid_barrier(unsigned ep) {
    __syncthreads();
    if (threadIdx.x == 0) {
        __threadfence();
        unsigned old = atomicAdd(&g_barc, 1u);
        if (old == gridDim.x - 1) {
            g_barc = 0;
            __threadfence();
            atomicExch(&g_barf, ep);
        } else {
            while ((int)(*(volatile unsigned*)&g_barf - ep) < 0) __nanosleep(32);
        }
    }
    __syncthreads();
}

// ---------------------------------------------------------------------------
// split conversions for input GEMM (unchanged)
// ---------------------------------------------------------------------------
__global__ void convA_kernel(const float* __restrict__ src, __nv_bfloat16* __restrict__ dst) {
    size_t i = (size_t)blockIdx.x * blockDim.x + threadIdx.x;
    int m = (int)(i >> 9), r = (int)(i & 511);
    float2 a = ((const float2*)src)[i];
    __nv_bfloat162 hi, lo;
    hi.x = __float2bfloat16(a.x); hi.y = __float2bfloat16(a.y);
    lo.x = __float2bfloat16(a.x - __bfloat162float(hi.x));
    lo.y = __float2bfloat16(a.y - __bfloat162float(hi.y));
    __nv_bfloat162* d = (__nv_bfloat162*)dst + (size_t)m * 1536;
    d[r] = hi; d[512 + r] = lo; d[1024 + r] = hi;
}

__global__ void convB_kernel(const float* __restrict__ W, __nv_bfloat16* __restrict__ dst) {
    __shared__ float t[32][33];
    int nb = blockIdx.x * 32, kb = blockIdx.y * 32;
    int tx = threadIdx.x & 31, ty = threadIdx.x >> 5;
    #pragma unroll
    for (int i = 0; i < 4; i++)
        t[ty + i * 8][tx] = W[(size_t)(kb + ty + i * 8) * SIXH + nb + tx];
    __syncthreads();
    #pragma unroll
    for (int i = 0; i < 4; i++) {
        int ny = ty + i * 8;
        float a = t[tx][ny];
        __nv_bfloat16 hi = __float2bfloat16(a);
        __nv_bfloat16 lo = __float2bfloat16(a - __bfloat162float(hi));
        __nv_bfloat16* dr = dst + (size_t)(nb + ny) * GK;
        dr[kb + tx] = hi; dr[1024 + kb + tx] = hi; dr[2048 + kb + tx] = lo;
    }
}

// ---------------------------------------------------------------------------
// input-projection GEMM (unchanged from R5)
// ---------------------------------------------------------------------------
__global__ void __launch_bounds__(512, 1) gemm_mma(const __nv_bfloat16* __restrict__ A,
                                                   const __nv_bfloat16* __restrict__ B) {
    extern __shared__ __align__(1024) char sm[];
    const uint32_t sbase = smem_u32(sm);
    const int tid = threadIdx.x, wid = tid >> 5, lane = tid & 31;
    const int n0 = blockIdx.x * GNT, m0 = blockIdx.y * GMT;
    const int m_warp = (wid & 1) * 64;
    const int n_warp = (wid >> 1) * 32;

    const int ahalf = lane >> 4;
    const int bhalf = (lane >> 3) & 1;
    int aoff[4], a7[4], boff[2], b7[2];
    #pragma unroll
    for (int mt = 0; mt < 4; mt++) {
        int r = m_warp + mt * 16 + (lane & 15);
        aoff[mt] = r * 128; a7[mt] = r & 7;
    }
    #pragma unroll
    for (int bt = 0; bt < 2; bt++) {
        int r = n_warp + bt * 16 + (lane & 7) + ((lane >> 4) << 3);
        boff[bt] = r * 128; b7[bt] = r & 7;
    }

    float acc[4][4][4];
    #pragma unroll
    for (int i = 0; i < 4; i++)
        #pragma unroll
        for (int j = 0; j < 4; j++)
            #pragma unroll
            for (int k = 0; k < 4; k++) acc[i][j][k] = 0.f;

    auto load_chunk = [&](int kc, int buf) {
        uint32_t sa = sbase + buf * GSTAGE;
        uint32_t sb = sa + 16384;
        const char* ga = (const char*)(A + (size_t)m0 * GK + kc * GKC);
        const char* gb = (const char*)(B + (size_t)n0 * GK + kc * GKC);
        #pragma unroll
        for (int i = 0; i < 2; i++) {
            int idx = tid + i * 512, r = idx >> 3, c = idx & 7;
            cp_async16(sa + r * 128 + (((c ^ (r & 7)) << 4)), ga + (size_t)r * (GK * 2) + c * 16);
        }
        #pragma unroll
        for (int i = 0; i < 4; i++) {
            int idx = tid + i * 512, r = idx >> 3, c = idx & 7;
            cp_async16(sb + r * 128 + (((c ^ (r & 7)) << 4)), gb + (size_t)r * (GK * 2) + c * 16);
        }
        asm volatile("cp.async.commit_group;" ::: "memory");
    };

    load_chunk(0, 0);
    for (int kc = 0; kc < GNCHUNK; kc++) {
        int buf = kc & 1;
        if (kc + 1 < GNCHUNK) {
            load_chunk(kc + 1, buf ^ 1);
            asm volatile("cp.async.wait_group 1;" ::: "memory");
        } else {
            asm volatile("cp.async.wait_group 0;" ::: "memory");
        }
        __syncthreads();

        uint32_t saA = sbase + buf * GSTAGE;
        uint32_t saB = saA + 16384;
        #pragma unroll
        for (int ks = 0; ks < 4; ks++) {
            uint32_t a[4][4], b[4][2];
            #pragma unroll
            for (int mt = 0; mt < 4; mt++) {
                uint32_t addr = saA + aoff[mt] + ((((ks << 1) + ahalf) ^ a7[mt]) << 4);
                ldsm_x4(addr, a[mt][0], a[mt][1], a[mt][2], a[mt][3]);
            }
            #pragma unroll
            for (int bt = 0; bt < 2; bt++) {
                uint32_t addr = saB + boff[bt] + ((((ks << 1) + bhalf) ^ b7[bt]) << 4);
                ldsm_x4(addr, b[2 * bt][0], b[2 * bt][1], b[2 * bt + 1][0], b[2 * bt + 1][1]);
            }
            #pragma unroll
            for (int mt = 0; mt < 4; mt++)
                #pragma unroll
                for (int nt = 0; nt < 4; nt++)
                    mma16816(acc[mt][nt], a[mt], b[nt]);
        }
        __syncthreads();
    }

    #pragma unroll
    for (int mt = 0; mt < 4; mt++) {
        int m = m0 + m_warp + mt * 16 + (lane >> 2);
        #pragma unroll
        for (int nt = 0; nt < 4; nt++) {
            int n = n0 + n_warp + nt * 8 + (lane & 3) * 2;
            *(float2*)(g_pi + (size_t)m * SIXH + n) = make_float2(acc[mt][nt][0], acc[mt][nt][1]);
            *(float2*)(g_pi + (size_t)(m + 8) * SIXH + n) = make_float2(acc[mt][nt][2], acc[mt][nt][3]);
        }
    }
}

// ---------------------------------------------------------------------------
// Pack recurrent weights: block jb, 32 chunks (16 hi + 16 lo), swizzled image
// of [40 n-rows x 64 k] bf16 per chunk (5120 B), n = gate*1024 + jb*8 + (nn&7).
// ---------------------------------------------------------------------------
__global__ void packw_kernel(const float* __restrict__ Ws) {
    size_t idx = (size_t)blockIdx.x * blockDim.x + threadIdx.x;
    if (idx >= 128ull * 32 * 40 * 64) return;
    int kk = (int)(idx & 63); size_t r = idx >> 6;
    int nn = (int)(r % 40); r /= 40;
    int wc = (int)(r & 31); int jb = (int)(r >> 5);
    int g = nn >> 3, jj = jb * 8 + (nn & 7);
    int k = (wc & 15) * 64 + kk;
    float v = Ws[(size_t)k * FIVEH + g * HH + jj];
    __nv_bfloat16 hi = __float2bfloat16(v);
    __nv_bfloat16 o = (wc < 16) ? hi : __float2bfloat16(v - __bfloat162float(hi));
    size_t off = ((size_t)(jb * 32 + wc)) * 2560 + nn * 64 + (((kk >> 3) ^ (nn & 7)) << 3) + (kk & 7);
    g_Wr[off] = o;
}

// ---------------------------------------------------------------------------
// Persistent recurrent kernel, tensor-core edition.
// 128 blocks x 256 threads; block jb owns j = jb*8..jb*8+7 (40 N-cols).
// Per step: ps = h_split @ W_split via mma.sync over 32 bulk-staged chunks,
// then gates in registers, h re-split/published, one grid barrier.
// ---------------------------------------------------------------------------
__global__ void __launch_bounds__(256, 1) rec_kernel(
    const float* __restrict__ bs, const int* __restrict__ lengths,
    float* __restrict__ y, float* __restrict__ outh, float* __restrict__ outc)
{
    extern __shared__ __align__(1024) char sm[];
    __shared__ __align__(8) unsigned long long s_mb[NSTG];
    __shared__ unsigned s_base;
    const uint32_t sbase = smem_u32(sm);
    float* ps_s = (float*)(sm + PS_OFF);

    const int tid = threadIdx.x, wid = tid >> 5, lane = tid & 31;
    const int jb = blockIdx.x;
    const int mt = wid & 3, kh = wid >> 2;
    const int w = wid;                      // gate-phase hidden column owner
    const int j = jb * 8 + w;
    const int r0 = lane, r1 = lane + 32;

    if (tid == 0) {
        s_base = *(volatile unsigned*)&g_barf;
        #pragma unroll
        for (int s = 0; s < NSTG; s++) mbar_init(smem_u32(&s_mb[s]), 1);
        asm volatile("fence.proxy.async.shared::cta;" ::: "memory");
    }
    // zero A' buffer 0 (initial h = 0); 16384 uint4 total
    {
        int zi = jb * 256 + tid;
        if (zi < 16384) ((uint4*)g_Ah)[zi] = make_uint4(0, 0, 0, 0);
    }

    const int len0 = lengths[r0], len1 = lengths[r1];
    float bias[5];
    #pragma unroll
    for (int g = 0; g < 5; g++) bias[g] = bs[g * HH + j];

    __syncthreads();
    unsigned ep = s_base;
    grid_barrier(++ep);

    // ldmatrix address components (sw = lane&7 for all tiles)
    const int sw = lane & 7;
    const uint32_t aRow = (uint32_t)((mt * 16 + (lane & 15)) * 128);
    const int ah = lane >> 4;
    const uint32_t bRow0 = (uint32_t)((((lane & 7) + ((lane >> 4) << 3))) * 128);
    const uint32_t bRow1 = bRow0 + 16 * 128;
    const uint32_t bRow2 = (uint32_t)((32 + (lane & 7)) * 128);
    const int bh = (lane >> 3) & 1;

    const char* Wbase = (const char*)(g_Wr + (size_t)jb * 32 * 2560);

    float h0 = 0.f, h1 = 0.f, c0 = 0.f, c1 = 0.f;

    for (int t = 0; t < TT; t++) {
        const char* Abase = (const char*)(g_Ah[t & 1]);

        auto issue = [&](int c) {
            int s = c & 3;
            uint32_t mb = smem_u32(&s_mb[s]);
            uint32_t st = sbase + s * STGB;
            if (c < 16) {
                mbar_expect(mb, 18432u);
                bulk_g2s(st, Abase + (size_t)c * 8192, 8192, mb);
                bulk_g2s(st + 8192, Wbase + (size_t)c * 5120, 5120, mb);
                bulk_g2s(st + 13312, Wbase + (size_t)(16 + c) * 5120, 5120, mb);
            } else {
                mbar_expect(mb, 13312u);
                bulk_g2s(st, Abase + (size_t)c * 8192, 8192, mb);
                bulk_g2s(st + 8192, Wbase + (size_t)(c - 16) * 5120, 5120, mb);
            }
        };
        if (tid == 0) { issue(0); issue(1); issue(2); }

        // prefetch input projections (latency hidden under GEMM)
        float p0[6], p1[6];
        {
            const float* pr0 = g_pi + ((size_t)r0 * TT + t) * SIXH + j;
            const float* pr1 = g_pi + ((size_t)r1 * TT + t) * SIXH + j;
            #pragma unroll
            for (int g = 0; g < 6; g++) { p0[g] = pr0[g * HH]; p1[g] = pr1[g * HH]; }
        }

        float acc[5][4];
        #pragma unroll
        for (int g = 0; g < 5; g++)
            #pragma unroll
            for (int q = 0; q < 4; q++) acc[g][q] = 0.f;

        for (int c = 0; c < 32; c++) {
            int s = c & 3;
            mbar_wait(smem_u32(&s_mb[s]), (c >> 2) & 1);
            uint32_t sA = sbase + s * STGB;
            int nslot = (c < 16) ? 2 : 1;
            #pragma unroll
            for (int sub = 0; sub < 2; sub++) {
                int gg = (kh * 2 + sub) * 2;
                uint32_t a[4];
                ldsm_x4(sA + aRow + (((gg + ah) ^ sw) << 4), a[0], a[1], a[2], a[3]);
                for (int slot = 0; slot < nslot; slot++) {
                    uint32_t sW = sA + 8192 + slot * 5120;
                    uint32_t b[5][2];
                    uint32_t gb = (uint32_t)(((gg + bh) ^ sw) << 4);
                    ldsm_x4(sW + bRow0 + gb, b[0][0], b[0][1], b[1][0], b[1][1]);
                    ldsm_x4(sW + bRow1 + gb, b[2][0], b[2][1], b[3][0], b[3][1]);
                    ldsm_x2(sW + bRow2 + gb, b[4][0], b[4][1]);
                    #pragma unroll
                    for (int g = 0; g < 5; g++) mma16816(acc[g], a, b[g]);
                }
            }
            __syncthreads();
            if (tid == 0 && c + 3 < 32) issue(c + 3);
        }

        // reduce partial ps into smem
        {
            float* pb = ps_s + kh * (64 * PS_PAD);
            int rr = mt * 16 + (lane >> 2);
            #pragma unroll
            for (int g = 0; g < 5; g++) {
                int cc = g * 8 + (lane & 3) * 2;
                pb[rr * PS_PAD + cc] = acc[g][0];
                pb[rr * PS_PAD + cc + 1] = acc[g][1];
                pb[(rr + 8) * PS_PAD + cc] = acc[g][2];
                pb[(rr + 8) * PS_PAD + cc + 1] = acc[g][3];
            }
        }
        __syncthreads();

        // gate phase: warp w owns hidden column j; lane owns b = lane, lane+32
        __nv_bfloat16* Aw = g_Ah[(t + 1) & 1];
        {
            float a0[5], a1[5];
            #pragma unroll
            for (int g = 0; g < 5; g++) {
                int cc = g * 8 + w;
                a0[g] = bias[g] + ps_s[r0 * PS_PAD + cc] + ps_s[64 * PS_PAD + r0 * PS_PAD + cc];
                a1[g] = bias[g] + ps_s[r1 * PS_PAD + cc] + ps_s[64 * PS_PAD + r1 * PS_PAD + cc];
            }
            {
                float ig = sigf(p0[0] + a0[0]), fg = sigf(p0[1] + a0[1]);
                float mi = tanhf(p0[2] + a0[2]), og = sigf(p0[3] + a0[3]);
                float cn = ig * mi + fg * c0;
                float o = og * tanhf(cn);
                float hg = sigf(p0[4] + a0[4]);
                o = hg * o + (1.f - hg) * p0[5];
                bool v = (t < len0);
                if (v) { c0 = cn; h0 = o; }
                y[((size_t)r0 * TT + t) * HH + j] = v ? o : 0.f;
            }
            {
                float ig = sigf(p1[0] + a1[0]), fg = sigf(p1[1] + a1[1]);
                float mi = tanhf(p1[2] + a1[2]), og = sigf(p1[3] + a1[3]);
                float cn = ig * mi + fg * c1;
                float o = og * tanhf(cn);
                float hg = sigf(p1[4] + a1[4]);
                o = hg * o + (1.f - hg) * p1[5];
                bool v = (t < len1);
                if (v) { c1 = cn; h1 = o; }
                y[((size_t)r1 * TT + t) * HH + j] = v ? o : 0.f;
            }
            // publish split h into swizzled A' chunks
            int kk = j & 63, cj = j >> 6;
            #pragma unroll
            for (int q = 0; q < 2; q++) {
                int b = q ? r1 : r0;
                float hv = q ? h1 : h0;
                __nv_bfloat16 hi = __float2bfloat16(hv);
                __nv_bfloat16 lo = __float2bfloat16(hv - __bfloat162float(hi));
                int pos = b * 64 + (((kk >> 3) ^ (b & 7)) << 3) + (kk & 7);
                Aw[cj * 4096 + pos] = hi;
                Aw[(16 + cj) * 4096 + pos] = lo;
            }
        }

        grid_barrier(++ep);
    }

    outh[(size_t)r0 * HH + j] = h0;
    outh[(size_t)r1 * HH + j] = h1;
    outc[(size_t)r0 * HH + j] = c0;
    outc[(size_t)r1 * HH + j] = c1;
}

extern "C" void kernel_launch(void* const* d_in, const int* in_sizes, int n_in,
                              void* d_out, int out_size)
{
    (void)in_sizes; (void)n_in; (void)out_size;
    const float* x   = (const float*)d_in[0];
    const int*   len = (const int*)d_in[1];
    const float* Wi0 = (const float*)d_in[2];
    const float* Ws0 = (const float*)d_in[3];
    const float* bs0 = (const float*)d_in[4];
    const float* Wi1 = (const float*)d_in[5];
    const float* Ws1 = (const float*)d_in[6];
    const float* bs1 = (const float*)d_in[7];
    float* out = (float*)d_out;

    float* y0_ptr = nullptr;
    cudaGetSymbolAddress((void**)&y0_ptr, g_y0);
    __nv_bfloat16* abf = nullptr; cudaGetSymbolAddress((void**)&abf, g_Abf);
    __nv_bfloat16* bbf = nullptr; cudaGetSymbolAddress((void**)&bbf, g_Bbf);

    cudaFuncSetAttribute(gemm_mma, cudaFuncAttributeMaxDynamicSharedMemorySize, SMEM_GEMM);
    cudaFuncSetAttribute(rec_kernel, cudaFuncAttributeMaxDynamicSharedMemorySize, SMEM_REC);

    float* outh = out + BTH;
    float* outc = out + BTH + 2 * BH;

    dim3 ggrid(SIXH / GNT, (BB * TT) / GMT);
    dim3 cbgrid(SIXH / 32, 1024 / 32);
    const int convA_blocks = (int)(((size_t)32768 * 512) / 256);
    const int packw_blocks = (int)((128ull * 32 * 40 * 64) / 256);

    // ---- layer 0 ----
    packw_kernel<<<packw_blocks, 256>>>(Ws0);
    convA_kernel<<<convA_blocks, 256>>>(x, abf);
    convB_kernel<<<cbgrid, 256>>>(Wi0, bbf);
    gemm_mma<<<ggrid, 512, SMEM_GEMM>>>(abf, bbf);
    rec_kernel<<<NBLK, 256, SMEM_REC>>>(bs0, len, y0_ptr, outh, outc);

    // ---- layer 1 ----
    packw_kernel<<<packw_blocks, 256>>>(Ws1);
    convA_kernel<<<convA_blocks, 256>>>(y0_ptr, abf);
    convB_kernel<<<cbgrid, 256>>>(Wi1, bbf);
    gemm_mma<<<ggrid, 512, SMEM_GEMM>>>(abf, bbf);
    rec_kernel<<<NBLK, 256, SMEM_REC>>>(bs1, len, out, outh + BH, outc + BH);
}

// round 8
// speedup vs baseline: 2.8050x; 1.0536x over previous
#include <cuda_runtime.h>
#include <cuda_bf16.h>
#include <cstdint>
#include <math.h>

#define BB 64
#define TT 512
#define DD 1024
#define HH 1024
#define SIXH (6 * HH)
#define FIVEH (5 * HH)
#define BTH (BB * TT * HH)
#define BH (BB * HH)

#define NBLK 128

// input-projection GEMM (unchanged)
#define GK 3072
#define GKC 64
#define GNCHUNK (GK / GKC)
#define GMT 128
#define GNT 256
#define GSTAGE 49152
#define SMEM_GEMM (2 * GSTAGE)

// recurrent kernel: W resident in smem; A streamed in a 4-stage ring
#define NSTG 4
#define ASTG 8192
#define WSM 163840                         // 32 chunks x 5120 B
#define A_OFF WSM
#define PS_OFF (WSM + NSTG * ASTG)         // 196608
#define PS_PAD 42
#define HSTG_OFF (PS_OFF + 2 * 64 * PS_PAD * 4)  // 218112
#define YSTG_OFF (HSTG_OFF + 2048)               // 220160
#define SMEM_REC (YSTG_OFF + 2048)               // 222208

__device__ __align__(16) float g_pi[201326592];
__device__ __align__(16) float g_y0[BTH];
__device__ __align__(16) __nv_bfloat16 g_Abf[98304ull * 1024ull];
__device__ __align__(16) __nv_bfloat16 g_Bbf[6144ull * 3072ull];
__device__ __align__(128) __nv_bfloat16 g_Wr[128ull * 32ull * 2560ull];
__device__ __align__(128) __nv_bfloat16 g_Ah[2][131072];

__device__ unsigned g_barc = 0;
__device__ unsigned g_barf = 0;

__device__ __forceinline__ float sigf(float x) { return 1.f / (1.f + expf(-x)); }

__device__ __forceinline__ uint32_t smem_u32(const void* p) {
    uint32_t a;
    asm("{ .reg .u64 t; cvta.to.shared.u64 t, %1; cvt.u32.u64 %0, t; }" : "=r"(a) : "l"(p));
    return a;
}
__device__ __forceinline__ void cp_async16(uint32_t d, const void* g) {
    asm volatile("cp.async.cg.shared.global [%0], [%1], 16;" :: "r"(d), "l"(g));
}
__device__ __forceinline__ void ldsm_x4(uint32_t addr, uint32_t& r0, uint32_t& r1,
                                        uint32_t& r2, uint32_t& r3) {
    asm volatile("ldmatrix.sync.aligned.m8n8.x4.shared.b16 {%0,%1,%2,%3}, [%4];"
                 : "=r"(r0), "=r"(r1), "=r"(r2), "=r"(r3) : "r"(addr));
}
__device__ __forceinline__ void ldsm_x2(uint32_t addr, uint32_t& r0, uint32_t& r1) {
    asm volatile("ldmatrix.sync.aligned.m8n8.x2.shared.b16 {%0,%1}, [%2];"
                 : "=r"(r0), "=r"(r1) : "r"(addr));
}
__device__ __forceinline__ void mma16816(float* c, const uint32_t* a, const uint32_t* b) {
    asm volatile("mma.sync.aligned.m16n8k16.row.col.f32.bf16.bf16.f32 "
                 "{%0,%1,%2,%3}, {%4,%5,%6,%7}, {%8,%9}, {%0,%1,%2,%3};"
                 : "+f"(c[0]), "+f"(c[1]), "+f"(c[2]), "+f"(c[3])
                 : "r"(a[0]), "r"(a[1]), "r"(a[2]), "r"(a[3]), "r"(b[0]), "r"(b[1]));
}
__device__ __forceinline__ void mbar_init(uint32_t a, uint32_t c) {
    asm volatile("mbarrier.init.shared.b64 [%0], %1;" :: "r"(a), "r"(c) : "memory");
}
__device__ __forceinline__ void mbar_expect(uint32_t a, uint32_t bytes) {
    asm volatile("mbarrier.arrive.expect_tx.shared.b64 _, [%0], %1;" :: "r"(a), "r"(bytes) : "memory");
}
__device__ __forceinline__ void mbar_wait(uint32_t a, uint32_t par) {
    uint32_t done;
    asm volatile("{\n\t.reg .pred p;\n\t"
                 "mbarrier.try_wait.parity.acquire.cta.shared::cta.b64 p, [%1], %2;\n\t"
                 "selp.b32 %0,1,0,p;\n\t}" : "=r"(done) : "r"(a), "r"(par) : "memory");
    while (!done) {
        asm volatile("{\n\t.reg .pred p;\n\t"
                     "mbarrier.try_wait.parity.acquire.cta.shared::cta.b64 p, [%1], %2, 0x989680;\n\t"
                     "selp.b32 %0,1,0,p;\n\t}" : "=r"(done) : "r"(a), "r"(par) : "memory");
    }
}
__device__ __forceinline__ void bulk_g2s(uint32_t dst, const void* src, uint32_t bytes, uint32_t mbar) {
    asm volatile("cp.async.bulk.shared::cluster.global.mbarrier::complete_tx::bytes [%0], [%1], %2, [%3];"
                 :: "r"(dst), "l"(src), "r"(bytes), "r"(mbar) : "memory");
}

__device__ __forceinline__ void grid_barrier(unsigned ep) {
    __syncthreads();
    if (threadIdx.x == 0) {
        __threadfence();
        unsigned old = atomicAdd(&g_barc, 1u);
        if (old == gridDim.x - 1) {
            g_barc = 0;
            __threadfence();
            atomicExch(&g_barf, ep);
        } else {
            while ((int)(*(volatile unsigned*)&g_barf - ep) < 0) { }
        }
    }
    __syncthreads();
}

// ---------------------------------------------------------------------------
__global__ void convA_kernel(const float* __restrict__ src, __nv_bfloat16* __restrict__ dst) {
    size_t i = (size_t)blockIdx.x * blockDim.x + threadIdx.x;
    int m = (int)(i >> 9), r = (int)(i & 511);
    float2 a = ((const float2*)src)[i];
    __nv_bfloat162 hi, lo;
    hi.x = __float2bfloat16(a.x); hi.y = __float2bfloat16(a.y);
    lo.x = __float2bfloat16(a.x - __bfloat162float(hi.x));
    lo.y = __float2bfloat16(a.y - __bfloat162float(hi.y));
    __nv_bfloat162* d = (__nv_bfloat162*)dst + (size_t)m * 1536;
    d[r] = hi; d[512 + r] = lo; d[1024 + r] = hi;
}

__global__ void convB_kernel(const float* __restrict__ W, __nv_bfloat16* __restrict__ dst) {
    __shared__ float t[32][33];
    int nb = blockIdx.x * 32, kb = blockIdx.y * 32;
    int tx = threadIdx.x & 31, ty = threadIdx.x >> 5;
    #pragma unroll
    for (int i = 0; i < 4; i++)
        t[ty + i * 8][tx] = W[(size_t)(kb + ty + i * 8) * SIXH + nb + tx];
    __syncthreads();
    #pragma unroll
    for (int i = 0; i < 4; i++) {
        int ny = ty + i * 8;
        float a = t[tx][ny];
        __nv_bfloat16 hi = __float2bfloat16(a);
        __nv_bfloat16 lo = __float2bfloat16(a - __bfloat162float(hi));
        __nv_bfloat16* dr = dst + (size_t)(nb + ny) * GK;
        dr[kb + tx] = hi; dr[1024 + kb + tx] = hi; dr[2048 + kb + tx] = lo;
    }
}

// ---------------------------------------------------------------------------
__global__ void __launch_bounds__(512, 1) gemm_mma(const __nv_bfloat16* __restrict__ A,
                                                   const __nv_bfloat16* __restrict__ B) {
    extern __shared__ __align__(1024) char sm[];
    const uint32_t sbase = smem_u32(sm);
    const int tid = threadIdx.x, wid = tid >> 5, lane = tid & 31;
    const int n0 = blockIdx.x * GNT, m0 = blockIdx.y * GMT;
    const int m_warp = (wid & 1) * 64;
    const int n_warp = (wid >> 1) * 32;

    const int ahalf = lane >> 4;
    const int bhalf = (lane >> 3) & 1;
    int aoff[4], a7[4], boff[2], b7[2];
    #pragma unroll
    for (int mt = 0; mt < 4; mt++) {
        int r = m_warp + mt * 16 + (lane & 15);
        aoff[mt] = r * 128; a7[mt] = r & 7;
    }
    #pragma unroll
    for (int bt = 0; bt < 2; bt++) {
        int r = n_warp + bt * 16 + (lane & 7) + ((lane >> 4) << 3);
        boff[bt] = r * 128; b7[bt] = r & 7;
    }

    float acc[4][4][4];
    #pragma unroll
    for (int i = 0; i < 4; i++)
        #pragma unroll
        for (int j = 0; j < 4; j++)
            #pragma unroll
            for (int k = 0; k < 4; k++) acc[i][j][k] = 0.f;

    auto load_chunk = [&](int kc, int buf) {
        uint32_t sa = sbase + buf * GSTAGE;
        uint32_t sb = sa + 16384;
        const char* ga = (const char*)(A + (size_t)m0 * GK + kc * GKC);
        const char* gb = (const char*)(B + (size_t)n0 * GK + kc * GKC);
        #pragma unroll
        for (int i = 0; i < 2; i++) {
            int idx = tid + i * 512, r = idx >> 3, c = idx & 7;
            cp_async16(sa + r * 128 + (((c ^ (r & 7)) << 4)), ga + (size_t)r * (GK * 2) + c * 16);
        }
        #pragma unroll
        for (int i = 0; i < 4; i++) {
            int idx = tid + i * 512, r = idx >> 3, c = idx & 7;
            cp_async16(sb + r * 128 + (((c ^ (r & 7)) << 4)), gb + (size_t)r * (GK * 2) + c * 16);
        }
        asm volatile("cp.async.commit_group;" ::: "memory");
    };

    load_chunk(0, 0);
    for (int kc = 0; kc < GNCHUNK; kc++) {
        int buf = kc & 1;
        if (kc + 1 < GNCHUNK) {
            load_chunk(kc + 1, buf ^ 1);
            asm volatile("cp.async.wait_group 1;" ::: "memory");
        } else {
            asm volatile("cp.async.wait_group 0;" ::: "memory");
        }
        __syncthreads();

        uint32_t saA = sbase + buf * GSTAGE;
        uint32_t saB = saA + 16384;
        #pragma unroll
        for (int ks = 0; ks < 4; ks++) {
            uint32_t a[4][4], b[4][2];
            #pragma unroll
            for (int mt = 0; mt < 4; mt++) {
                uint32_t addr = saA + aoff[mt] + ((((ks << 1) + ahalf) ^ a7[mt]) << 4);
                ldsm_x4(addr, a[mt][0], a[mt][1], a[mt][2], a[mt][3]);
            }
            #pragma unroll
            for (int bt = 0; bt < 2; bt++) {
                uint32_t addr = saB + boff[bt] + ((((ks << 1) + bhalf) ^ b7[bt]) << 4);
                ldsm_x4(addr, b[2 * bt][0], b[2 * bt][1], b[2 * bt + 1][0], b[2 * bt + 1][1]);
            }
            #pragma unroll
            for (int mt = 0; mt < 4; mt++)
                #pragma unroll
                for (int nt = 0; nt < 4; nt++)
                    mma16816(acc[mt][nt], a[mt], b[nt]);
        }
        __syncthreads();
    }

    #pragma unroll
    for (int mt = 0; mt < 4; mt++) {
        int m = m0 + m_warp + mt * 16 + (lane >> 2);
        #pragma unroll
        for (int nt = 0; nt < 4; nt++) {
            int n = n0 + n_warp + nt * 8 + (lane & 3) * 2;
            *(float2*)(g_pi + (size_t)m * SIXH + n) = make_float2(acc[mt][nt][0], acc[mt][nt][1]);
            *(float2*)(g_pi + (size_t)(m + 8) * SIXH + n) = make_float2(acc[mt][nt][2], acc[mt][nt][3]);
        }
    }
}

// ---------------------------------------------------------------------------
__global__ void packw_kernel(const float* __restrict__ Ws) {
    size_t idx = (size_t)blockIdx.x * blockDim.x + threadIdx.x;
    if (idx >= 128ull * 32 * 40 * 64) return;
    int kk = (int)(idx & 63); size_t r = idx >> 6;
    int nn = (int)(r % 40); r /= 40;
    int wc = (int)(r & 31); int jb = (int)(r >> 5);
    int g = nn >> 3, jj = jb * 8 + (nn & 7);
    int k = (wc & 15) * 64 + kk;
    float v = Ws[(size_t)k * FIVEH + g * HH + jj];
    __nv_bfloat16 hi = __float2bfloat16(v);
    __nv_bfloat16 o = (wc < 16) ? hi : __float2bfloat16(v - __bfloat162float(hi));
    size_t off = ((size_t)(jb * 32 + wc)) * 2560 + nn * 64 + (((kk >> 3) ^ (nn & 7)) << 3) + (kk & 7);
    g_Wr[off] = o;
}

// ---------------------------------------------------------------------------
// Persistent recurrent kernel: W resident in smem, A streamed per step.
// ---------------------------------------------------------------------------
__global__ void __launch_bounds__(256, 1) rec_kernel(
    const float* __restrict__ bs, const int* __restrict__ lengths,
    float* __restrict__ y, float* __restrict__ outh, float* __restrict__ outc)
{
    extern __shared__ __align__(1024) char sm[];
    __shared__ __align__(8) unsigned long long s_mb[NSTG];
    __shared__ __align__(8) unsigned long long s_mbw;
    __shared__ unsigned s_base;
    const uint32_t sbase = smem_u32(sm);
    float* ps_s = (float*)(sm + PS_OFF);
    __nv_bfloat16* hstg = (__nv_bfloat16*)(sm + HSTG_OFF);   // [2][64][8]
    float* ystg = (float*)(sm + YSTG_OFF);                    // [64][8]

    const int tid = threadIdx.x, wid = tid >> 5, lane = tid & 31;
    const int jb = blockIdx.x;
    const int mt = wid & 3, kh = wid >> 2;
    const int w = wid;
    const int j = jb * 8 + w;
    const int r0 = lane, r1 = lane + 32;
    const int cj = jb >> 3, kxor = jb & 7;

    const char* Wbase = (const char*)(g_Wr + (size_t)jb * 32 * 2560);

    if (tid == 0) {
        s_base = *(volatile unsigned*)&g_barf;
        #pragma unroll
        for (int s = 0; s < NSTG; s++) mbar_init(smem_u32(&s_mb[s]), 1);
        mbar_init(smem_u32(&s_mbw), 1);
        asm volatile("fence.proxy.async.shared::cta;" ::: "memory");
        // resident-weight load (once per layer)
        uint32_t mbw = smem_u32(&s_mbw);
        mbar_expect(mbw, (uint32_t)WSM);
        #pragma unroll
        for (int i = 0; i < 32; i++)
            bulk_g2s(sbase + i * 5120, Wbase + (size_t)i * 5120, 5120, mbw);
    }
    // zero A' buffer 0 (initial h = 0)
    {
        int zi = jb * 256 + tid;
        if (zi < 16384) ((uint4*)g_Ah)[zi] = make_uint4(0, 0, 0, 0);
    }

    const int len0 = lengths[r0], len1 = lengths[r1];
    float bias[5];
    #pragma unroll
    for (int g = 0; g < 5; g++) bias[g] = bs[g * HH + j];

    __syncthreads();
    unsigned ep = s_base;
    grid_barrier(++ep);
    mbar_wait(smem_u32(&s_mbw), 0);

    const int sw = lane & 7;
    const uint32_t aRow = (uint32_t)((mt * 16 + (lane & 15)) * 128);
    const int ah = lane >> 4;
    const uint32_t bRow0 = (uint32_t)((((lane & 7) + ((lane >> 4) << 3))) * 128);
    const uint32_t bRow1 = bRow0 + 16 * 128;
    const uint32_t bRow2 = (uint32_t)((32 + (lane & 7)) * 128);
    const int bh = (lane >> 3) & 1;

    float h0 = 0.f, h1 = 0.f, c0 = 0.f, c1 = 0.f;

    for (int t = 0; t < TT; t++) {
        const char* Abase = (const char*)(g_Ah[t & 1]);

        auto issueA = [&](int c) {
            int s = c & 3;
            uint32_t mb = smem_u32(&s_mb[s]);
            mbar_expect(mb, (uint32_t)ASTG);
            bulk_g2s(sbase + A_OFF + s * ASTG, Abase + (size_t)c * ASTG, ASTG, mb);
        };
        if (tid == 0) { issueA(0); issueA(1); issueA(2); issueA(3); }

        float p0[6], p1[6];
        {
            const float* pr0 = g_pi + ((size_t)r0 * TT + t) * SIXH + j;
            const float* pr1 = g_pi + ((size_t)r1 * TT + t) * SIXH + j;
            #pragma unroll
            for (int g = 0; g < 6; g++) { p0[g] = pr0[g * HH]; p1[g] = pr1[g * HH]; }
        }

        float acc[5][4];
        #pragma unroll
        for (int g = 0; g < 5; g++)
            #pragma unroll
            for (int q = 0; q < 4; q++) acc[g][q] = 0.f;

        for (int c = 0; c < 32; c++) {
            mbar_wait(smem_u32(&s_mb[c & 3]), (c >> 2) & 1);
            uint32_t sA = sbase + A_OFF + (c & 3) * ASTG;
            int wc0 = (c < 16) ? c : (c - 16);
            int ns = (c < 16) ? 2 : 1;
            #pragma unroll
            for (int sub = 0; sub < 2; sub++) {
                int gg = (kh * 2 + sub) * 2;
                uint32_t a[4];
                ldsm_x4(sA + aRow + (((gg + ah) ^ sw) << 4), a[0], a[1], a[2], a[3]);
                for (int slot = 0; slot < ns; slot++) {
                    uint32_t sW = sbase + (uint32_t)(wc0 + slot * 16) * 5120;
                    uint32_t b[5][2];
                    uint32_t gb = (uint32_t)(((gg + bh) ^ sw) << 4);
                    ldsm_x4(sW + bRow0 + gb, b[0][0], b[0][1], b[1][0], b[1][1]);
                    ldsm_x4(sW + bRow1 + gb, b[2][0], b[2][1], b[3][0], b[3][1]);
                    ldsm_x2(sW + bRow2 + gb, b[4][0], b[4][1]);
                    #pragma unroll
                    for (int g = 0; g < 5; g++) mma16816(acc[g], a, b[g]);
                }
            }
            __syncthreads();
            if (tid == 0 && c + 4 < 32) issueA(c + 4);
        }

        {
            float* pb = ps_s + kh * (64 * PS_PAD);
            int rr = mt * 16 + (lane >> 2);
            #pragma unroll
            for (int g = 0; g < 5; g++) {
                int cc = g * 8 + (lane & 3) * 2;
                pb[rr * PS_PAD + cc] = acc[g][0];
                pb[rr * PS_PAD + cc + 1] = acc[g][1];
                pb[(rr + 8) * PS_PAD + cc] = acc[g][2];
                pb[(rr + 8) * PS_PAD + cc + 1] = acc[g][3];
            }
        }
        __syncthreads();

        // gate phase: warp w owns hidden column j; lanes own b = lane, lane+32
        {
            float a0[5], a1[5];
            #pragma unroll
            for (int g = 0; g < 5; g++) {
                int cc = g * 8 + w;
                a0[g] = bias[g] + ps_s[r0 * PS_PAD + cc] + ps_s[64 * PS_PAD + r0 * PS_PAD + cc];
                a1[g] = bias[g] + ps_s[r1 * PS_PAD + cc] + ps_s[64 * PS_PAD + r1 * PS_PAD + cc];
            }
            {
                float ig = sigf(p0[0] + a0[0]), fg = sigf(p0[1] + a0[1]);
                float mi = tanhf(p0[2] + a0[2]), og = sigf(p0[3] + a0[3]);
                float cn = ig * mi + fg * c0;
                float o = og * tanhf(cn);
                float hg = sigf(p0[4] + a0[4]);
                o = hg * o + (1.f - hg) * p0[5];
                bool v = (t < len0);
                if (v) { c0 = cn; h0 = o; }
                ystg[r0 * 8 + w] = v ? o : 0.f;
            }
            {
                float ig = sigf(p1[0] + a1[0]), fg = sigf(p1[1] + a1[1]);
                float mi = tanhf(p1[2] + a1[2]), og = sigf(p1[3] + a1[3]);
                float cn = ig * mi + fg * c1;
                float o = og * tanhf(cn);
                float hg = sigf(p1[4] + a1[4]);
                o = hg * o + (1.f - hg) * p1[5];
                bool v = (t < len1);
                if (v) { c1 = cn; h1 = o; }
                ystg[r1 * 8 + w] = v ? o : 0.f;
            }
            #pragma unroll
            for (int q = 0; q < 2; q++) {
                float hv = q ? h1 : h0;
                int b = q ? r1 : r0;
                __nv_bfloat16 hi = __float2bfloat16(hv);
                __nv_bfloat16 lo = __float2bfloat16(hv - __bfloat162float(hi));
                hstg[b * 8 + w] = hi;
                hstg[512 + b * 8 + w] = lo;
            }
        }
        __syncthreads();

        // coalesced publish: h split (16B per row) + y (two 16B per row)
        __nv_bfloat16* Aw = g_Ah[(t + 1) & 1];
        if (tid < 128) {
            int q = tid >> 6, b = tid & 63;
            uint4 v = *(uint4*)&hstg[q * 512 + b * 8];
            size_t off = (size_t)(q * 16 + cj) * 4096 + b * 64 + ((kxor ^ (b & 7)) << 3);
            *(uint4*)(Aw + off) = v;
        } else {
            int hb = (tid - 128) >> 6, b = tid & 63;
            float4 v = *(float4*)&ystg[b * 8 + hb * 4];
            *(float4*)(y + ((size_t)b * TT + t) * HH + jb * 8 + hb * 4) = v;
        }

        grid_barrier(++ep);
    }

    outh[(size_t)r0 * HH + j] = h0;
    outh[(size_t)r1 * HH + j] = h1;
    outc[(size_t)r0 * HH + j] = c0;
    outc[(size_t)r1 * HH + j] = c1;
}

extern "C" void kernel_launch(void* const* d_in, const int* in_sizes, int n_in,
                              void* d_out, int out_size)
{
    (void)in_sizes; (void)n_in; (void)out_size;
    const float* x   = (const float*)d_in[0];
    const int*   len = (const int*)d_in[1];
    const float* Wi0 = (const float*)d_in[2];
    const float* Ws0 = (const float*)d_in[3];
    const float* bs0 = (const float*)d_in[4];
    const float* Wi1 = (const float*)d_in[5];
    const float* Ws1 = (const float*)d_in[6];
    const float* bs1 = (const float*)d_in[7];
    float* out = (float*)d_out;

    float* y0_ptr = nullptr;
    cudaGetSymbolAddress((void**)&y0_ptr, g_y0);
    __nv_bfloat16* abf = nullptr; cudaGetSymbolAddress((void**)&abf, g_Abf);
    __nv_bfloat16* bbf = nullptr; cudaGetSymbolAddress((void**)&bbf, g_Bbf);

    cudaFuncSetAttribute(gemm_mma, cudaFuncAttributeMaxDynamicSharedMemorySize, SMEM_GEMM);
    cudaFuncSetAttribute(rec_kernel, cudaFuncAttributeMaxDynamicSharedMemorySize, SMEM_REC);

    float* outh = out + BTH;
    float* outc = out + BTH + 2 * BH;

    dim3 ggrid(SIXH / GNT, (BB * TT) / GMT);
    dim3 cbgrid(SIXH / 32, 1024 / 32);
    const int convA_blocks = (int)(((size_t)32768 * 512) / 256);
    const int packw_blocks = (int)((128ull * 32 * 40 * 64) / 256);

    // ---- layer 0 ----
    packw_kernel<<<packw_blocks, 256>>>(Ws0);
    convA_kernel<<<convA_blocks, 256>>>(x, abf);
    convB_kernel<<<cbgrid, 256>>>(Wi0, bbf);
    gemm_mma<<<ggrid, 512, SMEM_GEMM>>>(abf, bbf);
    rec_kernel<<<NBLK, 256, SMEM_REC>>>(bs0, len, y0_ptr, outh, outc);

    // ---- layer 1 ----
    packw_kernel<<<packw_blocks, 256>>>(Ws1);
    convA_kernel<<<convA_blocks, 256>>>(y0_ptr, abf);
    convB_kernel<<<cbgrid, 256>>>(Wi1, bbf);
    gemm_mma<<<ggrid, 512, SMEM_GEMM>>>(abf, bbf);
    rec_kernel<<<NBLK, 256, SMEM_REC>>>(bs1, len, out, outh + BH, outc + BH);
}

// round 9
// speedup vs baseline: 2.9881x; 1.0653x over previous
#include <cuda_runtime.h>
#include <cuda_bf16.h>
#include <cstdint>
#include <math.h>

#define BB 64
#define TT 512
#define DD 1024
#define HH 1024
#define SIXH (6 * HH)
#define FIVEH (5 * HH)
#define BTH (BB * TT * HH)
#define BH (BB * HH)

#define NBLK 128

// input-projection GEMM (unchanged)
#define GK 3072
#define GKC 64
#define GNCHUNK (GK / GKC)
#define GMT 128
#define GNT 256
#define GSTAGE 49152
#define SMEM_GEMM (2 * GSTAGE)

// recurrent kernel: W resident in smem; A streamed in a 4-stage cp.async ring
#define NSTG 4
#define ASTG 8192
#define WSM 163840                         // 32 chunks x 5120 B
#define A_OFF WSM
#define PS_OFF (WSM + NSTG * ASTG)         // 196608
#define PS_PAD 42
#define HSTG_OFF (PS_OFF + 2 * 64 * PS_PAD * 4)  // 218112
#define YSTG_OFF (HSTG_OFF + 2048)               // 220160
#define SMEM_REC (YSTG_OFF + 2048)               // 222208

__device__ __align__(16) float g_pi[201326592];
__device__ __align__(16) float g_y0[BTH];
__device__ __align__(16) __nv_bfloat16 g_Abf[98304ull * 1024ull];
__device__ __align__(16) __nv_bfloat16 g_Bbf[6144ull * 3072ull];
__device__ __align__(128) __nv_bfloat16 g_Wr[128ull * 32ull * 2560ull];
__device__ __align__(128) __nv_bfloat16 g_Ah[2][131072];

// hierarchical grid barrier state (monotonic counters; replay-safe)
__device__ unsigned g_cnt[8];
__device__ unsigned g_cntm;
__device__ unsigned g_rel;

__device__ __forceinline__ float sigf(float x) { return 1.f / (1.f + expf(-x)); }

__device__ __forceinline__ uint32_t smem_u32(const void* p) {
    uint32_t a;
    asm("{ .reg .u64 t; cvta.to.shared.u64 t, %1; cvt.u32.u64 %0, t; }" : "=r"(a) : "l"(p));
    return a;
}
__device__ __forceinline__ void cp_async16(uint32_t d, const void* g) {
    asm volatile("cp.async.cg.shared.global [%0], [%1], 16;" :: "r"(d), "l"(g));
}
__device__ __forceinline__ void ldsm_x4(uint32_t addr, uint32_t& r0, uint32_t& r1,
                                        uint32_t& r2, uint32_t& r3) {
    asm volatile("ldmatrix.sync.aligned.m8n8.x4.shared.b16 {%0,%1,%2,%3}, [%4];"
                 : "=r"(r0), "=r"(r1), "=r"(r2), "=r"(r3) : "r"(addr));
}
__device__ __forceinline__ void ldsm_x2(uint32_t addr, uint32_t& r0, uint32_t& r1) {
    asm volatile("ldmatrix.sync.aligned.m8n8.x2.shared.b16 {%0,%1}, [%2];"
                 : "=r"(r0), "=r"(r1) : "r"(addr));
}
__device__ __forceinline__ void mma16816(float* c, const uint32_t* a, const uint32_t* b) {
    asm volatile("mma.sync.aligned.m16n8k16.row.col.f32.bf16.bf16.f32 "
                 "{%0,%1,%2,%3}, {%4,%5,%6,%7}, {%8,%9}, {%0,%1,%2,%3};"
                 : "+f"(c[0]), "+f"(c[1]), "+f"(c[2]), "+f"(c[3])
                 : "r"(a[0]), "r"(a[1]), "r"(a[2]), "r"(a[3]), "r"(b[0]), "r"(b[1]));
}

// hierarchical epoch barrier: 8 group counters -> master -> release word
__device__ __forceinline__ void grid_barrier(unsigned ep, int jb) {
    __syncthreads();
    if (threadIdx.x == 0) {
        __threadfence();
        unsigned v = atomicAdd(&g_cnt[jb & 7], 1u) + 1u;
        if (v == ep * 16u) {
            unsigned m = atomicAdd(&g_cntm, 1u) + 1u;
            if (m == ep * 8u) {
                atomicExch(&g_rel, ep);
            }
        }
        while (*(volatile unsigned*)&g_rel < ep) { }
    }
    __syncthreads();
}

// ---------------------------------------------------------------------------
__global__ void convA_kernel(const float* __restrict__ src, __nv_bfloat16* __restrict__ dst) {
    size_t i = (size_t)blockIdx.x * blockDim.x + threadIdx.x;
    int m = (int)(i >> 9), r = (int)(i & 511);
    float2 a = ((const float2*)src)[i];
    __nv_bfloat162 hi, lo;
    hi.x = __float2bfloat16(a.x); hi.y = __float2bfloat16(a.y);
    lo.x = __float2bfloat16(a.x - __bfloat162float(hi.x));
    lo.y = __float2bfloat16(a.y - __bfloat162float(hi.y));
    __nv_bfloat162* d = (__nv_bfloat162*)dst + (size_t)m * 1536;
    d[r] = hi; d[512 + r] = lo; d[1024 + r] = hi;
}

__global__ void convB_kernel(const float* __restrict__ W, __nv_bfloat16* __restrict__ dst) {
    __shared__ float t[32][33];
    int nb = blockIdx.x * 32, kb = blockIdx.y * 32;
    int tx = threadIdx.x & 31, ty = threadIdx.x >> 5;
    #pragma unroll
    for (int i = 0; i < 4; i++)
        t[ty + i * 8][tx] = W[(size_t)(kb + ty + i * 8) * SIXH + nb + tx];
    __syncthreads();
    #pragma unroll
    for (int i = 0; i < 4; i++) {
        int ny = ty + i * 8;
        float a = t[tx][ny];
        __nv_bfloat16 hi = __float2bfloat16(a);
        __nv_bfloat16 lo = __float2bfloat16(a - __bfloat162float(hi));
        __nv_bfloat16* dr = dst + (size_t)(nb + ny) * GK;
        dr[kb + tx] = hi; dr[1024 + kb + tx] = hi; dr[2048 + kb + tx] = lo;
    }
}

// ---------------------------------------------------------------------------
__global__ void __launch_bounds__(512, 1) gemm_mma(const __nv_bfloat16* __restrict__ A,
                                                   const __nv_bfloat16* __restrict__ B) {
    extern __shared__ __align__(1024) char sm[];
    const uint32_t sbase = smem_u32(sm);
    const int tid = threadIdx.x, wid = tid >> 5, lane = tid & 31;
    const int n0 = blockIdx.x * GNT, m0 = blockIdx.y * GMT;
    const int m_warp = (wid & 1) * 64;
    const int n_warp = (wid >> 1) * 32;

    const int ahalf = lane >> 4;
    const int bhalf = (lane >> 3) & 1;
    int aoff[4], a7[4], boff[2], b7[2];
    #pragma unroll
    for (int mt = 0; mt < 4; mt++) {
        int r = m_warp + mt * 16 + (lane & 15);
        aoff[mt] = r * 128; a7[mt] = r & 7;
    }
    #pragma unroll
    for (int bt = 0; bt < 2; bt++) {
        int r = n_warp + bt * 16 + (lane & 7) + ((lane >> 4) << 3);
        boff[bt] = r * 128; b7[bt] = r & 7;
    }

    float acc[4][4][4];
    #pragma unroll
    for (int i = 0; i < 4; i++)
        #pragma unroll
        for (int j = 0; j < 4; j++)
            #pragma unroll
            for (int k = 0; k < 4; k++) acc[i][j][k] = 0.f;

    auto load_chunk = [&](int kc, int buf) {
        uint32_t sa = sbase + buf * GSTAGE;
        uint32_t sb = sa + 16384;
        const char* ga = (const char*)(A + (size_t)m0 * GK + kc * GKC);
        const char* gb = (const char*)(B + (size_t)n0 * GK + kc * GKC);
        #pragma unroll
        for (int i = 0; i < 2; i++) {
            int idx = tid + i * 512, r = idx >> 3, c = idx & 7;
            cp_async16(sa + r * 128 + (((c ^ (r & 7)) << 4)), ga + (size_t)r * (GK * 2) + c * 16);
        }
        #pragma unroll
        for (int i = 0; i < 4; i++) {
            int idx = tid + i * 512, r = idx >> 3, c = idx & 7;
            cp_async16(sb + r * 128 + (((c ^ (r & 7)) << 4)), gb + (size_t)r * (GK * 2) + c * 16);
        }
        asm volatile("cp.async.commit_group;" ::: "memory");
    };

    load_chunk(0, 0);
    for (int kc = 0; kc < GNCHUNK; kc++) {
        int buf = kc & 1;
        if (kc + 1 < GNCHUNK) {
            load_chunk(kc + 1, buf ^ 1);
            asm volatile("cp.async.wait_group 1;" ::: "memory");
        } else {
            asm volatile("cp.async.wait_group 0;" ::: "memory");
        }
        __syncthreads();

        uint32_t saA = sbase + buf * GSTAGE;
        uint32_t saB = saA + 16384;
        #pragma unroll
        for (int ks = 0; ks < 4; ks++) {
            uint32_t a[4][4], b[4][2];
            #pragma unroll
            for (int mt = 0; mt < 4; mt++) {
                uint32_t addr = saA + aoff[mt] + ((((ks << 1) + ahalf) ^ a7[mt]) << 4);
                ldsm_x4(addr, a[mt][0], a[mt][1], a[mt][2], a[mt][3]);
            }
            #pragma unroll
            for (int bt = 0; bt < 2; bt++) {
                uint32_t addr = saB + boff[bt] + ((((ks << 1) + bhalf) ^ b7[bt]) << 4);
                ldsm_x4(addr, b[2 * bt][0], b[2 * bt][1], b[2 * bt + 1][0], b[2 * bt + 1][1]);
            }
            #pragma unroll
            for (int mt = 0; mt < 4; mt++)
                #pragma unroll
                for (int nt = 0; nt < 4; nt++)
                    mma16816(acc[mt][nt], a[mt], b[nt]);
        }
        __syncthreads();
    }

    #pragma unroll
    for (int mt = 0; mt < 4; mt++) {
        int m = m0 + m_warp + mt * 16 + (lane >> 2);
        #pragma unroll
        for (int nt = 0; nt < 4; nt++) {
            int n = n0 + n_warp + nt * 8 + (lane & 3) * 2;
            *(float2*)(g_pi + (size_t)m * SIXH + n) = make_float2(acc[mt][nt][0], acc[mt][nt][1]);
            *(float2*)(g_pi + (size_t)(m + 8) * SIXH + n) = make_float2(acc[mt][nt][2], acc[mt][nt][3]);
        }
    }
}

// ---------------------------------------------------------------------------
__global__ void packw_kernel(const float* __restrict__ Ws) {
    size_t idx = (size_t)blockIdx.x * blockDim.x + threadIdx.x;
    if (idx >= 128ull * 32 * 40 * 64) return;
    int kk = (int)(idx & 63); size_t r = idx >> 6;
    int nn = (int)(r % 40); r /= 40;
    int wc = (int)(r & 31); int jb = (int)(r >> 5);
    int g = nn >> 3, jj = jb * 8 + (nn & 7);
    int k = (wc & 15) * 64 + kk;
    float v = Ws[(size_t)k * FIVEH + g * HH + jj];
    __nv_bfloat16 hi = __float2bfloat16(v);
    __nv_bfloat16 o = (wc < 16) ? hi : __float2bfloat16(v - __bfloat162float(hi));
    size_t off = ((size_t)(jb * 32 + wc)) * 2560 + nn * 64 + (((kk >> 3) ^ (nn & 7)) << 3) + (kk & 7);
    g_Wr[off] = o;
}

// ---------------------------------------------------------------------------
// Persistent recurrent kernel: W resident, A streamed via multi-thread
// cp.async ring (no mbarriers), hierarchical grid barrier.
// ---------------------------------------------------------------------------
__global__ void __launch_bounds__(256, 1) rec_kernel(
    const float* __restrict__ bs, const int* __restrict__ lengths,
    float* __restrict__ y, float* __restrict__ outh, float* __restrict__ outc)
{
    extern __shared__ __align__(1024) char sm[];
    __shared__ unsigned s_base;
    const uint32_t sbase = smem_u32(sm);
    float* ps_s = (float*)(sm + PS_OFF);
    __nv_bfloat16* hstg = (__nv_bfloat16*)(sm + HSTG_OFF);   // [2][64][8]
    float* ystg = (float*)(sm + YSTG_OFF);                    // [64][8]

    const int tid = threadIdx.x, wid = tid >> 5, lane = tid & 31;
    const int jb = blockIdx.x;
    const int mt = wid & 3, kh = wid >> 2;
    const int w = wid;
    const int j = jb * 8 + w;
    const int r0 = lane, r1 = lane + 32;
    const int cj = jb >> 3, kxor = jb & 7;

    const char* Wbase = (const char*)(g_Wr + (size_t)jb * 32 * 2560);

    if (tid == 0) s_base = *(volatile unsigned*)&g_rel;

    // resident W load: 160KB via cp.async from all threads
    #pragma unroll 8
    for (int i = 0; i < 40; i++) {
        int u = tid + i * 256;
        cp_async16(sbase + u * 16, Wbase + (size_t)u * 16);
    }
    asm volatile("cp.async.commit_group;" ::: "memory");

    // zero A' buffer 0 (initial h = 0)
    {
        int zi = jb * 128 + tid;
        if (zi < 16384) ((uint4*)g_Ah)[zi] = make_uint4(0, 0, 0, 0);
        zi += 128;
        if (zi < 16384 && (jb * 128 + tid) < 16256 + 128) {
            // covered below by full range loop
        }
    }
    // ensure full coverage: 16384 uint4 over 128 blocks x 256 threads
    {
        int zi = jb * 256 + tid;
        if (zi < 16384) ((uint4*)g_Ah)[zi] = make_uint4(0, 0, 0, 0);
    }

    const int len0 = lengths[r0], len1 = lengths[r1];
    float bias[5];
    #pragma unroll
    for (int g = 0; g < 5; g++) bias[g] = bs[g * HH + j];

    asm volatile("cp.async.wait_group 0;" ::: "memory");
    __syncthreads();
    unsigned ep = s_base;
    grid_barrier(++ep, jb);

    const int sw = lane & 7;
    const uint32_t aRow = (uint32_t)((mt * 16 + (lane & 15)) * 128);
    const int ah = lane >> 4;
    const uint32_t bRow0 = (uint32_t)((((lane & 7) + ((lane >> 4) << 3))) * 128);
    const uint32_t bRow1 = bRow0 + 16 * 128;
    const uint32_t bRow2 = (uint32_t)((32 + (lane & 7)) * 128);
    const int bh = (lane >> 3) & 1;
    const uint32_t adst = sbase + A_OFF + (uint32_t)(tid << 5);

    float h0 = 0.f, h1 = 0.f, c0 = 0.f, c1 = 0.f;

    for (int t = 0; t < TT; t++) {
        const char* Abase = (const char*)(g_Ah[t & 1]) + (tid << 5);

        auto issueA = [&](int c) {
            if (c < 32) {
                uint32_t d = adst + (uint32_t)((c & 3) * ASTG);
                const char* s = Abase + (size_t)c * ASTG;
                cp_async16(d, s);
                cp_async16(d + 16, s + 16);
            }
            asm volatile("cp.async.commit_group;" ::: "memory");
        };
        issueA(0); issueA(1); issueA(2);

        float p0[6], p1[6];
        {
            const float* pr0 = g_pi + ((size_t)r0 * TT + t) * SIXH + j;
            const float* pr1 = g_pi + ((size_t)r1 * TT + t) * SIXH + j;
            #pragma unroll
            for (int g = 0; g < 6; g++) { p0[g] = pr0[g * HH]; p1[g] = pr1[g * HH]; }
        }

        float acc[5][4];
        #pragma unroll
        for (int g = 0; g < 5; g++)
            #pragma unroll
            for (int q = 0; q < 4; q++) acc[g][q] = 0.f;

        for (int c = 0; c < 32; c++) {
            asm volatile("cp.async.wait_group 2;" ::: "memory");
            __syncthreads();
            issueA(c + 3);

            uint32_t sA = sbase + A_OFF + (c & 3) * ASTG;
            int wc0 = (c < 16) ? c : (c - 16);
            int ns = (c < 16) ? 2 : 1;
            #pragma unroll
            for (int sub = 0; sub < 2; sub++) {
                int gg = (kh * 2 + sub) * 2;
                uint32_t a[4];
                ldsm_x4(sA + aRow + (((gg + ah) ^ sw) << 4), a[0], a[1], a[2], a[3]);
                for (int slot = 0; slot < ns; slot++) {
                    uint32_t sW = sbase + (uint32_t)(wc0 + slot * 16) * 5120;
                    uint32_t b[5][2];
                    uint32_t gb = (uint32_t)(((gg + bh) ^ sw) << 4);
                    ldsm_x4(sW + bRow0 + gb, b[0][0], b[0][1], b[1][0], b[1][1]);
                    ldsm_x4(sW + bRow1 + gb, b[2][0], b[2][1], b[3][0], b[3][1]);
                    ldsm_x2(sW + bRow2 + gb, b[4][0], b[4][1]);
                    #pragma unroll
                    for (int g = 0; g < 5; g++) mma16816(acc[g], a, b[g]);
                }
            }
        }
        __syncthreads();

        {
            float* pb = ps_s + kh * (64 * PS_PAD);
            int rr = mt * 16 + (lane >> 2);
            #pragma unroll
            for (int g = 0; g < 5; g++) {
                int cc = g * 8 + (lane & 3) * 2;
                pb[rr * PS_PAD + cc] = acc[g][0];
                pb[rr * PS_PAD + cc + 1] = acc[g][1];
                pb[(rr + 8) * PS_PAD + cc] = acc[g][2];
                pb[(rr + 8) * PS_PAD + cc + 1] = acc[g][3];
            }
        }
        __syncthreads();

        // gate phase: warp w owns hidden column j; lanes own b = lane, lane+32
        {
            float a0[5], a1[5];
            #pragma unroll
            for (int g = 0; g < 5; g++) {
                int cc = g * 8 + w;
                a0[g] = bias[g] + ps_s[r0 * PS_PAD + cc] + ps_s[64 * PS_PAD + r0 * PS_PAD + cc];
                a1[g] = bias[g] + ps_s[r1 * PS_PAD + cc] + ps_s[64 * PS_PAD + r1 * PS_PAD + cc];
            }
            {
                float ig = sigf(p0[0] + a0[0]), fg = sigf(p0[1] + a0[1]);
                float mi = tanhf(p0[2] + a0[2]), og = sigf(p0[3] + a0[3]);
                float cn = ig * mi + fg * c0;
                float o = og * tanhf(cn);
                float hg = sigf(p0[4] + a0[4]);
                o = hg * o + (1.f - hg) * p0[5];
                bool v = (t < len0);
                if (v) { c0 = cn; h0 = o; }
                ystg[r0 * 8 + w] = v ? o : 0.f;
            }
            {
                float ig = sigf(p1[0] + a1[0]), fg = sigf(p1[1] + a1[1]);
                float mi = tanhf(p1[2] + a1[2]), og = sigf(p1[3] + a1[3]);
                float cn = ig * mi + fg * c1;
                float o = og * tanhf(cn);
                float hg = sigf(p1[4] + a1[4]);
                o = hg * o + (1.f - hg) * p1[5];
                bool v = (t < len1);
                if (v) { c1 = cn; h1 = o; }
                ystg[r1 * 8 + w] = v ? o : 0.f;
            }
            #pragma unroll
            for (int q = 0; q < 2; q++) {
                float hv = q ? h1 : h0;
                int b = q ? r1 : r0;
                __nv_bfloat16 hi = __float2bfloat16(hv);
                __nv_bfloat16 lo = __float2bfloat16(hv - __bfloat162float(hi));
                hstg[b * 8 + w] = hi;
                hstg[512 + b * 8 + w] = lo;
            }
        }
        __syncthreads();

        // coalesced publish: h split (16B per row) + y (two 16B per row)
        __nv_bfloat16* Aw = g_Ah[(t + 1) & 1];
        if (tid < 128) {
            int q = tid >> 6, b = tid & 63;
            uint4 v = *(uint4*)&hstg[q * 512 + b * 8];
            size_t off = (size_t)(q * 16 + cj) * 4096 + b * 64 + ((kxor ^ (b & 7)) << 3);
            *(uint4*)(Aw + off) = v;
        } else {
            int hb = (tid - 128) >> 6, b = tid & 63;
            float4 v = *(float4*)&ystg[b * 8 + hb * 4];
            *(float4*)(y + ((size_t)b * TT + t) * HH + jb * 8 + hb * 4) = v;
        }

        grid_barrier(++ep, jb);
    }

    outh[(size_t)r0 * HH + j] = h0;
    outh[(size_t)r1 * HH + j] = h1;
    outc[(size_t)r0 * HH + j] = c0;
    outc[(size_t)r1 * HH + j] = c1;
}

extern "C" void kernel_launch(void* const* d_in, const int* in_sizes, int n_in,
                              void* d_out, int out_size)
{
    (void)in_sizes; (void)n_in; (void)out_size;
    const float* x   = (const float*)d_in[0];
    const int*   len = (const int*)d_in[1];
    const float* Wi0 = (const float*)d_in[2];
    const float* Ws0 = (const float*)d_in[3];
    const float* bs0 = (const float*)d_in[4];
    const float* Wi1 = (const float*)d_in[5];
    const float* Ws1 = (const float*)d_in[6];
    const float* bs1 = (const float*)d_in[7];
    float* out = (float*)d_out;

    float* y0_ptr = nullptr;
    cudaGetSymbolAddress((void**)&y0_ptr, g_y0);
    __nv_bfloat16* abf = nullptr; cudaGetSymbolAddress((void**)&abf, g_Abf);
    __nv_bfloat16* bbf = nullptr; cudaGetSymbolAddress((void**)&bbf, g_Bbf);

    cudaFuncSetAttribute(gemm_mma, cudaFuncAttributeMaxDynamicSharedMemorySize, SMEM_GEMM);
    cudaFuncSetAttribute(rec_kernel, cudaFuncAttributeMaxDynamicSharedMemorySize, SMEM_REC);

    float* outh = out + BTH;
    float* outc = out + BTH + 2 * BH;

    dim3 ggrid(SIXH / GNT, (BB * TT) / GMT);
    dim3 cbgrid(SIXH / 32, 1024 / 32);
    const int convA_blocks = (int)(((size_t)32768 * 512) / 256);
    const int packw_blocks = (int)((128ull * 32 * 40 * 64) / 256);

    // ---- layer 0 ----
    packw_kernel<<<packw_blocks, 256>>>(Ws0);
    convA_kernel<<<convA_blocks, 256>>>(x, abf);
    convB_kernel<<<cbgrid, 256>>>(Wi0, bbf);
    gemm_mma<<<ggrid, 512, SMEM_GEMM>>>(abf, bbf);
    rec_kernel<<<NBLK, 256, SMEM_REC>>>(bs0, len, y0_ptr, outh, outc);

    // ---- layer 1 ----
    packw_kernel<<<packw_blocks, 256>>>(Ws1);
    convA_kernel<<<convA_blocks, 256>>>(y0_ptr, abf);
    convB_kernel<<<cbgrid, 256>>>(Wi1, bbf);
    gemm_mma<<<ggrid, 512, SMEM_GEMM>>>(abf, bbf);
    rec_kernel<<<NBLK, 256, SMEM_REC>>>(bs1, len, out, outh + BH, outc + BH);
}